// round 5
// baseline (speedup 1.0000x reference)
#include <cuda_runtime.h>

#define NNODES 50000
#define NEDGES 600000
#define HFEAT  128
#define NCLASS 40
#define NEG_SLOPE 0.1f
#define NBLK 196   // ceil(NNODES/256)

// ---------------- device scratch (static, allocation-free) ----------------
__device__ int   g_deg[NNODES];
__device__ int   g_fill[NNODES];
__device__ int   g_rowptr[NNODES + 1];
__device__ int   g_col[NEDGES];
__device__ float g_inv[NNODES];
__device__ int   g_btot[NBLK];
__device__ int   g_boff[NBLK];
// raw hidden states (for aggregation input)
__device__ float g_hA [(size_t)NNODES * HFEAT];
__device__ float g_hB [(size_t)NNODES * HFEAT];
// split operands (tf32 hi/lo)
__device__ __align__(16) unsigned g_xH[(size_t)NNODES * HFEAT];
__device__ __align__(16) unsigned g_xL[(size_t)NNODES * HFEAT];
__device__ __align__(16) unsigned g_aggH[(size_t)NNODES * HFEAT];
__device__ __align__(16) unsigned g_aggL[(size_t)NNODES * HFEAT];
__device__ __align__(16) unsigned g_hAH[(size_t)NNODES * HFEAT];
__device__ __align__(16) unsigned g_hAL[(size_t)NNODES * HFEAT];
__device__ __align__(16) unsigned g_hBH[(size_t)NNODES * HFEAT];
__device__ __align__(16) unsigned g_hBL[(size_t)NNODES * HFEAT];
// decoder partials
__device__ float g_p[(size_t)NNODES * NCLASS];
__device__ float g_q[(size_t)NNODES * NCLASS];
// pre-split weights: [encWl|encWr|lay0Wl|lay0Wr|lay1Wl|lay1Wr] each 16384
__device__ __align__(16) unsigned g_Whi[6 * 16384];
__device__ __align__(16) unsigned g_Wlo[6 * 16384];
// dec: [decWl|decWr] each 5120
__device__ __align__(16) unsigned g_Dhi[2 * 5120];
__device__ __align__(16) unsigned g_Dlo[2 * 5120];

// ---------------- helpers ----------------
__device__ __forceinline__ void tf32_split(float v, unsigned& hi, unsigned& lo) {
    unsigned h;
    asm("cvt.rna.tf32.f32 %0, %1;" : "=r"(h) : "f"(v));
    float hf = __uint_as_float(h);
    float lf = v - hf;
    unsigned l;
    asm("cvt.rna.tf32.f32 %0, %1;" : "=r"(l) : "f"(lf));
    hi = h; lo = l;
}

__device__ __forceinline__ void mma_tf32(float* d, const unsigned* a, unsigned b0, unsigned b1) {
    asm volatile(
        "mma.sync.aligned.m16n8k8.row.col.f32.tf32.tf32.f32 "
        "{%0,%1,%2,%3}, {%4,%5,%6,%7}, {%8,%9}, {%0,%1,%2,%3};"
        : "+f"(d[0]), "+f"(d[1]), "+f"(d[2]), "+f"(d[3])
        : "r"(a[0]), "r"(a[1]), "r"(a[2]), "r"(a[3]), "r"(b0), "r"(b1));
}

__device__ __forceinline__ void cp16(void* dst, const void* src, bool pred) {
    unsigned d = (unsigned)__cvta_generic_to_shared(dst);
    int sz = pred ? 16 : 0;
    asm volatile("cp.async.cg.shared.global [%0], [%1], 16, %2;"
                 :: "r"(d), "l"(src), "r"(sz) : "memory");
}
__device__ __forceinline__ void cp_commit() {
    asm volatile("cp.async.commit_group;" ::: "memory");
}

// ---------------- weight / x pre-split ----------------
__global__ void k_splitW(const float* __restrict__ eWl, const float* __restrict__ eWr,
                         const float* __restrict__ lWl, const float* __restrict__ lWr,
                         const float* __restrict__ dWl, const float* __restrict__ dWr)
{
    int i = blockIdx.x * blockDim.x + threadIdx.x;
    if (i < 6 * 16384) {
        int m = i >> 14, off = i & 16383;
        const float* src = (m == 0) ? eWl : (m == 1) ? eWr : (m == 2) ? lWl :
                           (m == 3) ? lWr : (m == 4) ? lWl + 16384 : lWr + 16384;
        unsigned h, l;
        tf32_split(src[off], h, l);
        g_Whi[i] = h; g_Wlo[i] = l;
    } else if (i < 6 * 16384 + 2 * 5120) {
        int j = i - 6 * 16384;
        const float* src = (j < 5120) ? dWl : dWr;
        int off = (j < 5120) ? j : j - 5120;
        unsigned h, l;
        tf32_split(src[off], h, l);
        g_Dhi[j] = h; g_Dlo[j] = l;
    }
}

__global__ void k_splitX(const float* __restrict__ x) {
    int i = blockIdx.x * blockDim.x + threadIdx.x;
    if (i < NNODES * HFEAT) {
        unsigned h, l;
        tf32_split(x[i], h, l);
        g_xH[i] = h; g_xL[i] = l;
    }
}

// ---------------- CSR build ----------------
__global__ void k_zero() {
    int i = blockIdx.x * blockDim.x + threadIdx.x;
    if (i < NNODES) { g_deg[i] = 0; g_fill[i] = 0; }
}

__global__ void k_hist(const int* __restrict__ ei) {
    int e = blockIdx.x * blockDim.x + threadIdx.x;
    if (e < NEDGES) atomicAdd(&g_deg[ei[NEDGES + e]], 1);
}

__global__ void k_scan1() {
    __shared__ int wsum[8];
    int b = blockIdx.x, t = threadIdx.x;
    int idx = (b << 8) + t;
    int v = (idx < NNODES) ? g_deg[idx] : 0;
    int x = v;
    #pragma unroll
    for (int o = 1; o < 32; o <<= 1) {
        int y = __shfl_up_sync(0xFFFFFFFFu, x, o);
        if ((t & 31) >= o) x += y;
    }
    if ((t & 31) == 31) wsum[t >> 5] = x;
    __syncthreads();
    if (t == 0) {
        int c = 0;
        #pragma unroll
        for (int i = 0; i < 8; i++) { int y = wsum[i]; wsum[i] = c; c += y; }
    }
    __syncthreads();
    int incl = x + wsum[t >> 5];
    if (idx < NNODES) {
        g_rowptr[idx] = incl - v;
        g_inv[idx] = 1.0f / fmaxf((float)v, 1.0f);
    }
    if (t == 255) g_btot[b] = incl;
}

__global__ void k_scan2() {
    __shared__ int wsum[8];
    int t = threadIdx.x;
    int v = (t < NBLK) ? g_btot[t] : 0;
    int x = v;
    #pragma unroll
    for (int o = 1; o < 32; o <<= 1) {
        int y = __shfl_up_sync(0xFFFFFFFFu, x, o);
        if ((t & 31) >= o) x += y;
    }
    if ((t & 31) == 31) wsum[t >> 5] = x;
    __syncthreads();
    if (t == 0) {
        int c = 0;
        #pragma unroll
        for (int i = 0; i < 8; i++) { int y = wsum[i]; wsum[i] = c; c += y; }
    }
    __syncthreads();
    int incl = x + wsum[t >> 5];
    if (t < NBLK) g_boff[t] = incl - v;
    if (t == 255) g_rowptr[NNODES] = incl;
}

__global__ void k_scan3() {
    int b = blockIdx.x, t = threadIdx.x;
    int idx = (b << 8) + t;
    if (idx < NNODES) g_rowptr[idx] += g_boff[b];
}

__global__ void k_fill(const int* __restrict__ ei) {
    int e = blockIdx.x * blockDim.x + threadIdx.x;
    if (e < NEDGES) {
        int dst = ei[NEDGES + e];
        int pos = g_rowptr[dst] + atomicAdd(&g_fill[dst], 1);
        g_col[pos] = ei[e];
    }
}

// ---------------- mean aggregation, writes tf32-split output ----------------
__global__ void k_aggregate_split(const float* __restrict__ in) {
    int gw   = (blockIdx.x * blockDim.x + threadIdx.x) >> 5;
    int lane = threadIdx.x & 31;
    if (gw >= NNODES) return;
    int s = g_rowptr[gw], e = g_rowptr[gw + 1];
    float4 acc = make_float4(0.f, 0.f, 0.f, 0.f);
    int i = s;
    for (; i + 1 < e; i += 2) {
        int s0 = g_col[i], s1 = g_col[i + 1];
        float4 v0 = *(const float4*)(in + (size_t)s0 * HFEAT + lane * 4);
        float4 v1 = *(const float4*)(in + (size_t)s1 * HFEAT + lane * 4);
        acc.x += v0.x + v1.x; acc.y += v0.y + v1.y;
        acc.z += v0.z + v1.z; acc.w += v0.w + v1.w;
    }
    if (i < e) {
        int s0 = g_col[i];
        float4 v0 = *(const float4*)(in + (size_t)s0 * HFEAT + lane * 4);
        acc.x += v0.x; acc.y += v0.y; acc.z += v0.z; acc.w += v0.w;
    }
    float inv = g_inv[gw];
    uint4 h, l;
    tf32_split(acc.x * inv, h.x, l.x);
    tf32_split(acc.y * inv, h.y, l.y);
    tf32_split(acc.z * inv, h.z, l.z);
    tf32_split(acc.w * inv, h.w, l.w);
    *(uint4*)(g_aggH + (size_t)gw * HFEAT + lane * 4) = h;
    *(uint4*)(g_aggL + (size_t)gw * HFEAT + lane * 4) = l;
}

// ---------------- SAGE GEMM: cp.async double-buffered, pre-split operands ----------------
#define ASTR 20
#define BSTR 132

struct Stage128 {
    unsigned Ah[128 * ASTR];
    unsigned Al[128 * ASTR];
    unsigned Bh[16 * BSTR];
    unsigned Bl[16 * BSTR];
};

__global__ void __launch_bounds__(256, 2) k_gemm128(
    const unsigned* __restrict__ A1H, const unsigned* __restrict__ A1L,
    const unsigned* __restrict__ A2H, const unsigned* __restrict__ A2L,
    const unsigned* __restrict__ Whi0, const unsigned* __restrict__ Wlo0,
    const unsigned* __restrict__ Whi1, const unsigned* __restrict__ Wlo1,
    const float* __restrict__ bias, float* __restrict__ out,
    unsigned* __restrict__ outH, unsigned* __restrict__ outL)
{
    extern __shared__ unsigned smem_raw[];
    Stage128* st = reinterpret_cast<Stage128*>(smem_raw);

    int t = threadIdx.x;
    int lane = t & 31;
    int w = t >> 5;
    int rg = w >> 1;
    int cg = w & 1;
    int block_row = blockIdx.x * 128;

    float acc[2][8][4];
    #pragma unroll
    for (int i = 0; i < 2; i++)
        #pragma unroll
        for (int j = 0; j < 8; j++)
            #pragma unroll
            for (int q = 0; q < 4; q++) acc[i][j][q] = 0.f;

    auto prefetch = [&](int c, Stage128& s) {
        int pn = c >> 3, k0 = (c & 7) << 4;
        const unsigned* AH = pn ? A2H : A1H;
        const unsigned* AL = pn ? A2L : A1L;
        const unsigned* WH = pn ? Whi1 : Whi0;
        const unsigned* WL = pn ? Wlo1 : Wlo0;
        #pragma unroll
        for (int i = 0; i < 2; i++) {
            int idx = t + (i << 8);
            int r = idx >> 2, kk = (idx & 3) << 2;
            int gr = block_row + r;
            bool ok = gr < NNODES;
            int grc = ok ? gr : 0;
            cp16(&s.Ah[r * ASTR + kk], AH + (size_t)grc * 128 + k0 + kk, ok);
            cp16(&s.Al[r * ASTR + kk], AL + (size_t)grc * 128 + k0 + kk, ok);
            int kb = idx >> 5, n = (idx & 31) << 2;
            cp16(&s.Bh[kb * BSTR + n], WH + (size_t)(k0 + kb) * 128 + n, true);
            cp16(&s.Bl[kb * BSTR + n], WL + (size_t)(k0 + kb) * 128 + n, true);
        }
    };

    prefetch(0, st[0]); cp_commit();
    prefetch(1, st[1]); cp_commit();

    #pragma unroll 1
    for (int c = 0; c < 16; ++c) {
        if (c < 15) asm volatile("cp.async.wait_group 1;" ::: "memory");
        else        asm volatile("cp.async.wait_group 0;" ::: "memory");
        __syncthreads();
        Stage128& s = st[c & 1];

        #pragma unroll
        for (int ks = 0; ks < 2; ks++) {
            unsigned ah[2][4], al[2][4];
            int kc = (ks << 3) + (lane & 3);
            int rb = (rg << 5) + (lane >> 2);
            #pragma unroll
            for (int i = 0; i < 2; i++) {
                int r0 = rb + (i << 4);
                ah[i][0] = s.Ah[r0 * ASTR + kc];
                ah[i][1] = s.Ah[(r0 + 8) * ASTR + kc];
                ah[i][2] = s.Ah[r0 * ASTR + kc + 4];
                ah[i][3] = s.Ah[(r0 + 8) * ASTR + kc + 4];
                al[i][0] = s.Al[r0 * ASTR + kc];
                al[i][1] = s.Al[(r0 + 8) * ASTR + kc];
                al[i][2] = s.Al[r0 * ASTR + kc + 4];
                al[i][3] = s.Al[(r0 + 8) * ASTR + kc + 4];
            }
            #pragma unroll
            for (int j = 0; j < 8; j++) {
                int n0 = (cg << 6) + (j << 3) + (lane >> 2);
                int kb = (ks << 3) + (lane & 3);
                unsigned bh0 = s.Bh[kb * BSTR + n0];
                unsigned bh1 = s.Bh[(kb + 4) * BSTR + n0];
                unsigned bl0 = s.Bl[kb * BSTR + n0];
                unsigned bl1 = s.Bl[(kb + 4) * BSTR + n0];
                #pragma unroll
                for (int i = 0; i < 2; i++) {
                    mma_tf32(acc[i][j], al[i], bh0, bh1);
                    mma_tf32(acc[i][j], ah[i], bl0, bl1);
                    mma_tf32(acc[i][j], ah[i], bh0, bh1);
                }
            }
        }
        __syncthreads();
        if (c + 2 < 16) { prefetch(c + 2, st[c & 1]); cp_commit(); }
    }

    // epilogue: bias + leaky relu, write raw + split
    #pragma unroll
    for (int i = 0; i < 2; i++) {
        int r0 = block_row + (rg << 5) + (i << 4) + (lane >> 2);
        #pragma unroll
        for (int j = 0; j < 8; j++) {
            int c = (cg << 6) + (j << 3) + ((lane & 3) << 1);
            float bi0 = bias[c], bi1 = bias[c + 1];
            #pragma unroll
            for (int half = 0; half < 2; half++) {
                int r = r0 + half * 8;
                if (r < NNODES) {
                    float v0 = acc[i][j][2 * half + 0] + bi0;
                    float v1 = acc[i][j][2 * half + 1] + bi1;
                    v0 = v0 > 0.f ? v0 : NEG_SLOPE * v0;
                    v1 = v1 > 0.f ? v1 : NEG_SLOPE * v1;
                    size_t o = (size_t)r * 128 + c;
                    *(float2*)(out + o) = make_float2(v0, v1);
                    unsigned h0, l0, h1, l1;
                    tf32_split(v0, h0, l0);
                    tf32_split(v1, h1, l1);
                    *(uint2*)(outH + o) = make_uint2(h0, h1);
                    *(uint2*)(outL + o) = make_uint2(l0, l1);
                }
            }
        }
    }
}

// ---------------- decoder GEMM: p = A@Wl, q = A@Wr + b ----------------
#define BSTRD 44

struct StageDec {
    unsigned Ah[128 * ASTR];
    unsigned Al[128 * ASTR];
    unsigned B[4][16 * BSTRD];   // 0:WlH 1:WlL 2:WrH 3:WrL
};

__global__ void __launch_bounds__(256, 2) k_gemm_dec2(
    const unsigned* __restrict__ AH, const unsigned* __restrict__ AL,
    const unsigned* __restrict__ WlH, const unsigned* __restrict__ WlL,
    const unsigned* __restrict__ WrH, const unsigned* __restrict__ WrL,
    const float* __restrict__ bias)
{
    extern __shared__ unsigned smem_raw[];
    StageDec* st = reinterpret_cast<StageDec*>(smem_raw);

    int t = threadIdx.x;
    int lane = t & 31;
    int w = t >> 5;
    int block_row = blockIdx.x * 128;

    float accp[5][4], accq[5][4];
    #pragma unroll
    for (int j = 0; j < 5; j++)
        #pragma unroll
        for (int q = 0; q < 4; q++) { accp[j][q] = 0.f; accq[j][q] = 0.f; }

    auto prefetch = [&](int c, StageDec& s) {
        int k0 = c << 4;
        #pragma unroll
        for (int i = 0; i < 2; i++) {
            int idx = t + (i << 8);
            int r = idx >> 2, kk = (idx & 3) << 2;
            int gr = block_row + r;
            bool ok = gr < NNODES;
            int grc = ok ? gr : 0;
            cp16(&s.Ah[r * ASTR + kk], AH + (size_t)grc * 128 + k0 + kk, ok);
            cp16(&s.Al[r * ASTR + kk], AL + (size_t)grc * 128 + k0 + kk, ok);
        }
        const unsigned* wsrc[4] = { WlH, WlL, WrH, WrL };
        for (int i = t; i < 640; i += 256) {
            int arr = i / 160, rem = i % 160;
            int kb = rem / 10, n = (rem % 10) << 2;
            cp16(&s.B[arr][kb * BSTRD + n], wsrc[arr] + (size_t)(k0 + kb) * NCLASS + n, true);
        }
    };

    prefetch(0, st[0]); cp_commit();
    prefetch(1, st[1]); cp_commit();

    #pragma unroll 1
    for (int c = 0; c < 8; ++c) {
        if (c < 7) asm volatile("cp.async.wait_group 1;" ::: "memory");
        else       asm volatile("cp.async.wait_group 0;" ::: "memory");
        __syncthreads();
        StageDec& s = st[c & 1];

        #pragma unroll
        for (int ks = 0; ks < 2; ks++) {
            unsigned ah[4], al[4];
            int kc = (ks << 3) + (lane & 3);
            int r0 = (w << 4) + (lane >> 2);
            ah[0] = s.Ah[r0 * ASTR + kc];
            ah[1] = s.Ah[(r0 + 8) * ASTR + kc];
            ah[2] = s.Ah[r0 * ASTR + kc + 4];
            ah[3] = s.Ah[(r0 + 8) * ASTR + kc + 4];
            al[0] = s.Al[r0 * ASTR + kc];
            al[1] = s.Al[(r0 + 8) * ASTR + kc];
            al[2] = s.Al[r0 * ASTR + kc + 4];
            al[3] = s.Al[(r0 + 8) * ASTR + kc + 4];
            #pragma unroll
            for (int j = 0; j < 5; j++) {
                int n0 = (j << 3) + (lane >> 2);
                int kb = (ks << 3) + (lane & 3);
                unsigned bh0 = s.B[0][kb * BSTRD + n0];
                unsigned bh1 = s.B[0][(kb + 4) * BSTRD + n0];
                unsigned bl0 = s.B[1][kb * BSTRD + n0];
                unsigned bl1 = s.B[1][(kb + 4) * BSTRD + n0];
                mma_tf32(accp[j], al, bh0, bh1);
                mma_tf32(accp[j], ah, bl0, bl1);
                mma_tf32(accp[j], ah, bh0, bh1);
                unsigned ch0 = s.B[2][kb * BSTRD + n0];
                unsigned ch1 = s.B[2][(kb + 4) * BSTRD + n0];
                unsigned cl0 = s.B[3][kb * BSTRD + n0];
                unsigned cl1 = s.B[3][(kb + 4) * BSTRD + n0];
                mma_tf32(accq[j], al, ch0, ch1);
                mma_tf32(accq[j], ah, cl0, cl1);
                mma_tf32(accq[j], ah, ch0, ch1);
            }
        }
        __syncthreads();
        if (c + 2 < 8) { prefetch(c + 2, st[c & 1]); cp_commit(); }
    }

    int r0 = block_row + (w << 4) + (lane >> 2);
    int r1 = r0 + 8;
    #pragma unroll
    for (int j = 0; j < 5; j++) {
        int c = (j << 3) + ((lane & 3) << 1);
        float bi0 = bias[c], bi1 = bias[c + 1];
        if (r0 < NNODES) {
            *(float2*)(g_p + (size_t)r0 * NCLASS + c) = make_float2(accp[j][0], accp[j][1]);
            *(float2*)(g_q + (size_t)r0 * NCLASS + c) = make_float2(accq[j][0] + bi0, accq[j][1] + bi1);
        }
        if (r1 < NNODES) {
            *(float2*)(g_p + (size_t)r1 * NCLASS + c) = make_float2(accp[j][2], accp[j][3]);
            *(float2*)(g_q + (size_t)r1 * NCLASS + c) = make_float2(accq[j][2] + bi0, accq[j][3] + bi1);
        }
    }
}

// ---------------- final: aggregate p (40 cols) + q, log_softmax ----------------
__global__ void k_aggdec(float* __restrict__ out) {
    int gw   = (blockIdx.x * blockDim.x + threadIdx.x) >> 5;
    int lane = threadIdx.x & 31;
    if (gw >= NNODES) return;
    int s = g_rowptr[gw], e = g_rowptr[gw + 1];
    bool act = lane < 20;
    float ax = 0.f, ay = 0.f;
    int i = s;
    for (; i + 1 < e; i += 2) {
        int s0 = g_col[i], s1 = g_col[i + 1];
        if (act) {
            float2 v0 = *(const float2*)(g_p + (size_t)s0 * NCLASS + lane * 2);
            float2 v1 = *(const float2*)(g_p + (size_t)s1 * NCLASS + lane * 2);
            ax += v0.x + v1.x; ay += v0.y + v1.y;
        }
    }
    if (i < e) {
        int s0 = g_col[i];
        if (act) {
            float2 v0 = *(const float2*)(g_p + (size_t)s0 * NCLASS + lane * 2);
            ax += v0.x; ay += v0.y;
        }
    }
    float inv = g_inv[gw];
    float rx = -1e30f, ry = -1e30f;
    if (act) {
        float2 qq = *(const float2*)(g_q + (size_t)gw * NCLASS + lane * 2);
        rx = ax * inv + qq.x;
        ry = ay * inv + qq.y;
    }
    float m = fmaxf(rx, ry);
    #pragma unroll
    for (int o = 16; o; o >>= 1) m = fmaxf(m, __shfl_xor_sync(0xFFFFFFFFu, m, o));
    float ss = act ? (expf(rx - m) + expf(ry - m)) : 0.f;
    #pragma unroll
    for (int o = 16; o; o >>= 1) ss += __shfl_xor_sync(0xFFFFFFFFu, ss, o);
    float l = m + logf(ss);
    if (act) {
        *(float2*)(out + (size_t)gw * NCLASS + lane * 2) = make_float2(rx - l, ry - l);
    }
}

// ---------------- launch ----------------
extern "C" void kernel_launch(void* const* d_in, const int* in_sizes, int n_in,
                              void* d_out, int out_size) {
    const float* x      = (const float*)d_in[0];
    const int*   ei     = (const int*)  d_in[1];
    const float* enc_Wl = (const float*)d_in[2];
    const float* enc_Wr = (const float*)d_in[3];
    const float* enc_b  = (const float*)d_in[4];
    const float* lay_Wl = (const float*)d_in[5];
    const float* lay_Wr = (const float*)d_in[6];
    const float* lay_b  = (const float*)d_in[7];
    const float* dec_Wl = (const float*)d_in[8];
    const float* dec_Wr = (const float*)d_in[9];
    const float* dec_b  = (const float*)d_in[10];
    float* out = (float*)d_out;

    float *hA, *hB;
    unsigned *xH, *xL, *aggH, *aggL, *hAH, *hAL, *hBH, *hBL, *whi, *wlo, *dhi, *dlo;
    cudaGetSymbolAddress((void**)&hA,   g_hA);
    cudaGetSymbolAddress((void**)&hB,   g_hB);
    cudaGetSymbolAddress((void**)&xH,   g_xH);
    cudaGetSymbolAddress((void**)&xL,   g_xL);
    cudaGetSymbolAddress((void**)&aggH, g_aggH);
    cudaGetSymbolAddress((void**)&aggL, g_aggL);
    cudaGetSymbolAddress((void**)&hAH,  g_hAH);
    cudaGetSymbolAddress((void**)&hAL,  g_hAL);
    cudaGetSymbolAddress((void**)&hBH,  g_hBH);
    cudaGetSymbolAddress((void**)&hBL,  g_hBL);
    cudaGetSymbolAddress((void**)&whi,  g_Whi);
    cudaGetSymbolAddress((void**)&wlo,  g_Wlo);
    cudaGetSymbolAddress((void**)&dhi,  g_Dhi);
    cudaGetSymbolAddress((void**)&dlo,  g_Dlo);

    const int ZB = (NNODES + 255) / 256;
    const int EB = (NEDGES + 255) / 256;
    const int AGGB = (NNODES * 32 + 255) / 256;
    const int MB = (NNODES + 127) / 128;
    const int SW = (6 * 16384 + 2 * 5120 + 255) / 256;
    const int SX = (NNODES * HFEAT + 255) / 256;

    const int SMEM_G = sizeof(Stage128) * 2;
    const int SMEM_D = sizeof(StageDec) * 2;
    cudaFuncSetAttribute(k_gemm128,   cudaFuncAttributeMaxDynamicSharedMemorySize, SMEM_G);
    cudaFuncSetAttribute(k_gemm_dec2, cudaFuncAttributeMaxDynamicSharedMemorySize, SMEM_D);

    k_splitW<<<SW, 256>>>(enc_Wl, enc_Wr, lay_Wl, lay_Wr, dec_Wl, dec_Wr);
    k_splitX<<<SX, 256>>>(x);
    k_zero<<<ZB, 256>>>();
    k_hist<<<EB, 256>>>(ei);
    k_scan1<<<NBLK, 256>>>();
    k_scan2<<<1, 256>>>();
    k_scan3<<<NBLK, 256>>>();
    k_fill<<<EB, 256>>>(ei);

    // encoder
    k_aggregate_split<<<AGGB, 256>>>(x);
    k_gemm128<<<MB, 256, SMEM_G>>>(aggH, aggL, xH, xL,
                                   whi, wlo, whi + 16384, wlo + 16384,
                                   enc_b, hA, hAH, hAL);
    // layer 0
    k_aggregate_split<<<AGGB, 256>>>(hA);
    k_gemm128<<<MB, 256, SMEM_G>>>(aggH, aggL, hAH, hAL,
                                   whi + 2 * 16384, wlo + 2 * 16384,
                                   whi + 3 * 16384, wlo + 3 * 16384,
                                   lay_b, hB, hBH, hBL);
    // layer 1
    k_aggregate_split<<<AGGB, 256>>>(hB);
    k_gemm128<<<MB, 256, SMEM_G>>>(aggH, aggL, hBH, hBL,
                                   whi + 4 * 16384, wlo + 4 * 16384,
                                   whi + 5 * 16384, wlo + 5 * 16384,
                                   lay_b + HFEAT, hA, hAH, hAL);
    // decoder: p = hA@Wl, q = hA@Wr + b, then aggregate p + softmax
    k_gemm_dec2<<<MB, 256, SMEM_D>>>(hAH, hAL, dhi, dlo, dhi + 5120, dlo + 5120, dec_b);
    k_aggdec<<<AGGB, 256>>>(out);
}

// round 6
// speedup vs baseline: 1.1087x; 1.1087x over previous
#include <cuda_runtime.h>

#define NNODES 50000
#define NEDGES 600000
#define HFEAT  128
#define NCLASS 40
#define NEG_SLOPE 0.1f
#define NBLK 196   // ceil(NNODES/256)

// ---------------- device scratch (static, allocation-free) ----------------
__device__ int   g_deg[NNODES];
__device__ int   g_fill[NNODES];
__device__ int   g_rowptr[NNODES + 1];
__device__ int   g_col[NEDGES];
__device__ float g_inv[NNODES];
__device__ int   g_btot[NBLK];
__device__ int   g_boff[NBLK];
__device__ float g_agg[(size_t)NNODES * HFEAT];
__device__ float g_hA [(size_t)NNODES * HFEAT];
__device__ float g_hB [(size_t)NNODES * HFEAT];
// decoder partials
__device__ float g_p[(size_t)NNODES * NCLASS];
__device__ float g_q[(size_t)NNODES * NCLASS];
// pre-split weights: [encWl|encWr|lay0Wl|lay0Wr|lay1Wl|lay1Wr] each 16384
__device__ __align__(16) unsigned g_Whi[6 * 16384];
__device__ __align__(16) unsigned g_Wlo[6 * 16384];
// dec: [decWl|decWr] each 5120
__device__ __align__(16) unsigned g_Dhi[2 * 5120];
__device__ __align__(16) unsigned g_Dlo[2 * 5120];

// ---------------- helpers ----------------
__device__ __forceinline__ void tf32_split(float v, unsigned& hi, unsigned& lo) {
    unsigned h;
    asm("cvt.rna.tf32.f32 %0, %1;" : "=r"(h) : "f"(v));
    float hf = __uint_as_float(h);
    float lf = v - hf;
    unsigned l;
    asm("cvt.rna.tf32.f32 %0, %1;" : "=r"(l) : "f"(lf));
    hi = h; lo = l;
}

__device__ __forceinline__ void mma_tf32(float* d, const unsigned* a, unsigned b0, unsigned b1) {
    asm volatile(
        "mma.sync.aligned.m16n8k8.row.col.f32.tf32.tf32.f32 "
        "{%0,%1,%2,%3}, {%4,%5,%6,%7}, {%8,%9}, {%0,%1,%2,%3};"
        : "+f"(d[0]), "+f"(d[1]), "+f"(d[2]), "+f"(d[3])
        : "r"(a[0]), "r"(a[1]), "r"(a[2]), "r"(a[3]), "r"(b0), "r"(b1));
}

// ---------------- weight pre-split ----------------
__global__ void k_splitW(const float* __restrict__ eWl, const float* __restrict__ eWr,
                         const float* __restrict__ lWl, const float* __restrict__ lWr,
                         const float* __restrict__ dWl, const float* __restrict__ dWr)
{
    int i = blockIdx.x * blockDim.x + threadIdx.x;
    if (i < 6 * 16384) {
        int m = i >> 14, off = i & 16383;
        const float* src = (m == 0) ? eWl : (m == 1) ? eWr : (m == 2) ? lWl :
                           (m == 3) ? lWr : (m == 4) ? lWl + 16384 : lWr + 16384;
        unsigned h, l;
        tf32_split(src[off], h, l);
        g_Whi[i] = h; g_Wlo[i] = l;
    } else if (i < 6 * 16384 + 2 * 5120) {
        int j = i - 6 * 16384;
        const float* src = (j < 5120) ? dWl : dWr;
        int off = (j < 5120) ? j : j - 5120;
        unsigned h, l;
        tf32_split(src[off], h, l);
        g_Dhi[j] = h; g_Dlo[j] = l;
    }
}

// ---------------- CSR build ----------------
__global__ void k_zero() {
    int i = blockIdx.x * blockDim.x + threadIdx.x;
    if (i < NNODES) { g_deg[i] = 0; g_fill[i] = 0; }
}

__global__ void k_hist(const int* __restrict__ ei) {
    int e = blockIdx.x * blockDim.x + threadIdx.x;
    if (e < NEDGES) atomicAdd(&g_deg[ei[NEDGES + e]], 1);
}

__global__ void k_scan1() {
    __shared__ int wsum[8];
    int b = blockIdx.x, t = threadIdx.x;
    int idx = (b << 8) + t;
    int v = (idx < NNODES) ? g_deg[idx] : 0;
    int x = v;
    #pragma unroll
    for (int o = 1; o < 32; o <<= 1) {
        int y = __shfl_up_sync(0xFFFFFFFFu, x, o);
        if ((t & 31) >= o) x += y;
    }
    if ((t & 31) == 31) wsum[t >> 5] = x;
    __syncthreads();
    if (t == 0) {
        int c = 0;
        #pragma unroll
        for (int i = 0; i < 8; i++) { int y = wsum[i]; wsum[i] = c; c += y; }
    }
    __syncthreads();
    int incl = x + wsum[t >> 5];
    if (idx < NNODES) {
        g_rowptr[idx] = incl - v;
        g_inv[idx] = 1.0f / fmaxf((float)v, 1.0f);
    }
    if (t == 255) g_btot[b] = incl;
}

__global__ void k_scan2() {
    __shared__ int wsum[8];
    int t = threadIdx.x;
    int v = (t < NBLK) ? g_btot[t] : 0;
    int x = v;
    #pragma unroll
    for (int o = 1; o < 32; o <<= 1) {
        int y = __shfl_up_sync(0xFFFFFFFFu, x, o);
        if ((t & 31) >= o) x += y;
    }
    if ((t & 31) == 31) wsum[t >> 5] = x;
    __syncthreads();
    if (t == 0) {
        int c = 0;
        #pragma unroll
        for (int i = 0; i < 8; i++) { int y = wsum[i]; wsum[i] = c; c += y; }
    }
    __syncthreads();
    int incl = x + wsum[t >> 5];
    if (t < NBLK) g_boff[t] = incl - v;
    if (t == 255) g_rowptr[NNODES] = incl;
}

__global__ void k_scan3() {
    int b = blockIdx.x, t = threadIdx.x;
    int idx = (b << 8) + t;
    if (idx < NNODES) g_rowptr[idx] += g_boff[b];
}

__global__ void k_fill(const int* __restrict__ ei) {
    int e = blockIdx.x * blockDim.x + threadIdx.x;
    if (e < NEDGES) {
        int dst = ei[NEDGES + e];
        int pos = g_rowptr[dst] + atomicAdd(&g_fill[dst], 1);
        g_col[pos] = ei[e];
    }
}

// ---------------- mean aggregation: warp per destination node ----------------
__global__ void k_aggregate(const float* __restrict__ in, float* __restrict__ out) {
    int gw   = (blockIdx.x * blockDim.x + threadIdx.x) >> 5;
    int lane = threadIdx.x & 31;
    if (gw >= NNODES) return;
    int s = g_rowptr[gw], e = g_rowptr[gw + 1];
    float4 acc = make_float4(0.f, 0.f, 0.f, 0.f);
    int i = s;
    for (; i + 1 < e; i += 2) {
        int s0 = g_col[i], s1 = g_col[i + 1];
        float4 v0 = *(const float4*)(in + (size_t)s0 * HFEAT + lane * 4);
        float4 v1 = *(const float4*)(in + (size_t)s1 * HFEAT + lane * 4);
        acc.x += v0.x + v1.x; acc.y += v0.y + v1.y;
        acc.z += v0.z + v1.z; acc.w += v0.w + v1.w;
    }
    if (i < e) {
        int s0 = g_col[i];
        float4 v0 = *(const float4*)(in + (size_t)s0 * HFEAT + lane * 4);
        acc.x += v0.x; acc.y += v0.y; acc.z += v0.z; acc.w += v0.w;
    }
    float inv = g_inv[gw];
    float4 r = make_float4(acc.x * inv, acc.y * inv, acc.z * inv, acc.w * inv);
    *(float4*)(out + (size_t)gw * HFEAT + lane * 4) = r;
}

// ---------------- SAGE GEMM, 3xTF32, pipelined, pre-split W (round-4 proven) ----------------
#define ASTR 20
#define BSTR 132

__global__ void __launch_bounds__(256, 2) k_gemm128(
    const float* __restrict__ A1, const float* __restrict__ A2,
    const unsigned* __restrict__ Whi0, const unsigned* __restrict__ Wlo0,
    const unsigned* __restrict__ Whi1, const unsigned* __restrict__ Wlo1,
    const float* __restrict__ bias, float* __restrict__ out)
{
    __shared__ unsigned As_hi[128 * ASTR];
    __shared__ unsigned As_lo[128 * ASTR];
    __shared__ unsigned Bs_hi[16 * BSTR];
    __shared__ unsigned Bs_lo[16 * BSTR];

    int t = threadIdx.x;
    int lane = t & 31;
    int w = t >> 5;
    int rg = w >> 1;      // row group 0..3 (32 rows each)
    int cg = w & 1;       // col group 0..1 (64 cols each)
    int block_row = blockIdx.x * 128;

    float acc[2][8][4];
    #pragma unroll
    for (int i = 0; i < 2; i++)
        #pragma unroll
        for (int j = 0; j < 8; j++)
            #pragma unroll
            for (int q = 0; q < 4; q++) acc[i][j][q] = 0.f;

    float4 avP[2];
    uint4  bhP[2], blP[2];

    auto prefetch = [&](int c) {
        int pn = c >> 3, k0 = (c & 7) << 4;
        const float*    A  = pn ? A2 : A1;
        const unsigned* Wh = pn ? Whi1 : Whi0;
        const unsigned* Wl = pn ? Wlo1 : Wlo0;
        #pragma unroll
        for (int i = 0; i < 2; i++) {
            int idx = t + (i << 8);
            int r = idx >> 2, kk = (idx & 3) << 2;
            int gr = block_row + r;
            avP[i] = (gr < NNODES) ? *(const float4*)(A + (size_t)gr * 128 + k0 + kk)
                                   : make_float4(0.f, 0.f, 0.f, 0.f);
            int kb = idx >> 5, n = (idx & 31) << 2;
            bhP[i] = *(const uint4*)(Wh + (size_t)(k0 + kb) * 128 + n);
            blP[i] = *(const uint4*)(Wl + (size_t)(k0 + kb) * 128 + n);
        }
    };

    prefetch(0);

    #pragma unroll 1
    for (int c = 0; c < 16; ++c) {
        __syncthreads();
        #pragma unroll
        for (int i = 0; i < 2; i++) {
            int idx = t + (i << 8);
            int r = idx >> 2, kk = (idx & 3) << 2;
            uint4 h, l;
            tf32_split(avP[i].x, h.x, l.x);
            tf32_split(avP[i].y, h.y, l.y);
            tf32_split(avP[i].z, h.z, l.z);
            tf32_split(avP[i].w, h.w, l.w);
            *(uint4*)&As_hi[r * ASTR + kk] = h;
            *(uint4*)&As_lo[r * ASTR + kk] = l;
            int kb = idx >> 5, n = (idx & 31) << 2;
            *(uint4*)&Bs_hi[kb * BSTR + n] = bhP[i];
            *(uint4*)&Bs_lo[kb * BSTR + n] = blP[i];
        }
        __syncthreads();
        if (c < 15) prefetch(c + 1);

        #pragma unroll
        for (int ks = 0; ks < 2; ks++) {
            unsigned ah[2][4], al[2][4];
            int kc = (ks << 3) + (lane & 3);
            int rb = (rg << 5) + (lane >> 2);
            #pragma unroll
            for (int i = 0; i < 2; i++) {
                int r0 = rb + (i << 4);
                ah[i][0] = As_hi[r0 * ASTR + kc];
                ah[i][1] = As_hi[(r0 + 8) * ASTR + kc];
                ah[i][2] = As_hi[r0 * ASTR + kc + 4];
                ah[i][3] = As_hi[(r0 + 8) * ASTR + kc + 4];
                al[i][0] = As_lo[r0 * ASTR + kc];
                al[i][1] = As_lo[(r0 + 8) * ASTR + kc];
                al[i][2] = As_lo[r0 * ASTR + kc + 4];
                al[i][3] = As_lo[(r0 + 8) * ASTR + kc + 4];
            }
            #pragma unroll
            for (int j = 0; j < 8; j++) {
                int n0 = (cg << 6) + (j << 3) + (lane >> 2);
                int kb = (ks << 3) + (lane & 3);
                unsigned bh0 = Bs_hi[kb * BSTR + n0];
                unsigned bh1 = Bs_hi[(kb + 4) * BSTR + n0];
                unsigned bl0 = Bs_lo[kb * BSTR + n0];
                unsigned bl1 = Bs_lo[(kb + 4) * BSTR + n0];
                #pragma unroll
                for (int i = 0; i < 2; i++) {
                    mma_tf32(acc[i][j], al[i], bh0, bh1);
                    mma_tf32(acc[i][j], ah[i], bl0, bl1);
                    mma_tf32(acc[i][j], ah[i], bh0, bh1);
                }
            }
        }
    }

    // epilogue: bias + leaky relu
    #pragma unroll
    for (int i = 0; i < 2; i++) {
        int r0 = block_row + (rg << 5) + (i << 4) + (lane >> 2);
        #pragma unroll
        for (int j = 0; j < 8; j++) {
            int c = (cg << 6) + (j << 3) + ((lane & 3) << 1);
            float bi0 = bias[c], bi1 = bias[c + 1];
            if (r0 < NNODES) {
                float v0 = acc[i][j][0] + bi0;
                float v1 = acc[i][j][1] + bi1;
                v0 = v0 > 0.f ? v0 : NEG_SLOPE * v0;
                v1 = v1 > 0.f ? v1 : NEG_SLOPE * v1;
                *(float2*)(out + (size_t)r0 * 128 + c) = make_float2(v0, v1);
            }
            int r1 = r0 + 8;
            if (r1 < NNODES) {
                float v2 = acc[i][j][2] + bi0;
                float v3 = acc[i][j][3] + bi1;
                v2 = v2 > 0.f ? v2 : NEG_SLOPE * v2;
                v3 = v3 > 0.f ? v3 : NEG_SLOPE * v3;
                *(float2*)(out + (size_t)r1 * 128 + c) = make_float2(v2, v3);
            }
        }
    }
}

// ---------------- commuted decoder GEMM: p = A@Wl, q = A@Wr + b (N=40, K=128) ----------------
#define BSTRD 44

__global__ void __launch_bounds__(256, 2) k_gemm_dec2(
    const float* __restrict__ A,
    const unsigned* __restrict__ WlH, const unsigned* __restrict__ WlL,
    const unsigned* __restrict__ WrH, const unsigned* __restrict__ WrL,
    const float* __restrict__ bias)
{
    __shared__ unsigned As_hi[128 * ASTR];
    __shared__ unsigned As_lo[128 * ASTR];
    __shared__ unsigned Bs[4][16 * BSTRD];   // 0:WlH 1:WlL 2:WrH 3:WrL

    int t = threadIdx.x;
    int lane = t & 31;
    int w = t >> 5;               // warp 0..7, owns 16 rows
    int block_row = blockIdx.x * 128;

    float accp[5][4], accq[5][4];
    #pragma unroll
    for (int j = 0; j < 5; j++)
        #pragma unroll
        for (int q = 0; q < 4; q++) { accp[j][q] = 0.f; accq[j][q] = 0.f; }

    float4 avP[2];
    uint4  bP[4];
    bool bload = t < 160;

    auto prefetch = [&](int c) {
        int k0 = c << 4;
        #pragma unroll
        for (int i = 0; i < 2; i++) {
            int idx = t + (i << 8);
            int r = idx >> 2, kk = (idx & 3) << 2;
            int gr = block_row + r;
            avP[i] = (gr < NNODES) ? *(const float4*)(A + (size_t)gr * 128 + k0 + kk)
                                   : make_float4(0.f, 0.f, 0.f, 0.f);
        }
        if (bload) {
            int kk = t / 10, n = (t % 10) << 2;
            size_t o = (size_t)(k0 + kk) * NCLASS + n;
            bP[0] = *(const uint4*)(WlH + o);
            bP[1] = *(const uint4*)(WlL + o);
            bP[2] = *(const uint4*)(WrH + o);
            bP[3] = *(const uint4*)(WrL + o);
        }
    };

    prefetch(0);

    #pragma unroll 1
    for (int c = 0; c < 8; ++c) {
        __syncthreads();
        #pragma unroll
        for (int i = 0; i < 2; i++) {
            int idx = t + (i << 8);
            int r = idx >> 2, kk = (idx & 3) << 2;
            uint4 h, l;
            tf32_split(avP[i].x, h.x, l.x);
            tf32_split(avP[i].y, h.y, l.y);
            tf32_split(avP[i].z, h.z, l.z);
            tf32_split(avP[i].w, h.w, l.w);
            *(uint4*)&As_hi[r * ASTR + kk] = h;
            *(uint4*)&As_lo[r * ASTR + kk] = l;
        }
        if (bload) {
            int kk = t / 10, n = (t % 10) << 2;
            *(uint4*)&Bs[0][kk * BSTRD + n] = bP[0];
            *(uint4*)&Bs[1][kk * BSTRD + n] = bP[1];
            *(uint4*)&Bs[2][kk * BSTRD + n] = bP[2];
            *(uint4*)&Bs[3][kk * BSTRD + n] = bP[3];
        }
        __syncthreads();
        if (c < 7) prefetch(c + 1);

        #pragma unroll
        for (int ks = 0; ks < 2; ks++) {
            unsigned ah[4], al[4];
            int kc = (ks << 3) + (lane & 3);
            int r0 = (w << 4) + (lane >> 2);
            ah[0] = As_hi[r0 * ASTR + kc];
            ah[1] = As_hi[(r0 + 8) * ASTR + kc];
            ah[2] = As_hi[r0 * ASTR + kc + 4];
            ah[3] = As_hi[(r0 + 8) * ASTR + kc + 4];
            al[0] = As_lo[r0 * ASTR + kc];
            al[1] = As_lo[(r0 + 8) * ASTR + kc];
            al[2] = As_lo[r0 * ASTR + kc + 4];
            al[3] = As_lo[(r0 + 8) * ASTR + kc + 4];
            #pragma unroll
            for (int j = 0; j < 5; j++) {
                int n0 = (j << 3) + (lane >> 2);
                int kb = (ks << 3) + (lane & 3);
                unsigned bh0 = Bs[0][kb * BSTRD + n0];
                unsigned bh1 = Bs[0][(kb + 4) * BSTRD + n0];
                unsigned bl0 = Bs[1][kb * BSTRD + n0];
                unsigned bl1 = Bs[1][(kb + 4) * BSTRD + n0];
                mma_tf32(accp[j], al, bh0, bh1);
                mma_tf32(accp[j], ah, bl0, bl1);
                mma_tf32(accp[j], ah, bh0, bh1);
                unsigned ch0 = Bs[2][kb * BSTRD + n0];
                unsigned ch1 = Bs[2][(kb + 4) * BSTRD + n0];
                unsigned cl0 = Bs[3][kb * BSTRD + n0];
                unsigned cl1 = Bs[3][(kb + 4) * BSTRD + n0];
                mma_tf32(accq[j], al, ch0, ch1);
                mma_tf32(accq[j], ah, cl0, cl1);
                mma_tf32(accq[j], ah, ch0, ch1);
            }
        }
    }

    int r0 = block_row + (w << 4) + (lane >> 2);
    int r1 = r0 + 8;
    #pragma unroll
    for (int j = 0; j < 5; j++) {
        int c = (j << 3) + ((lane & 3) << 1);
        float bi0 = bias[c], bi1 = bias[c + 1];
        if (r0 < NNODES) {
            *(float2*)(g_p + (size_t)r0 * NCLASS + c) = make_float2(accp[j][0], accp[j][1]);
            *(float2*)(g_q + (size_t)r0 * NCLASS + c) = make_float2(accq[j][0] + bi0, accq[j][1] + bi1);
        }
        if (r1 < NNODES) {
            *(float2*)(g_p + (size_t)r1 * NCLASS + c) = make_float2(accp[j][2], accp[j][3]);
            *(float2*)(g_q + (size_t)r1 * NCLASS + c) = make_float2(accq[j][2] + bi0, accq[j][3] + bi1);
        }
    }
}

// ---------------- final: aggregate p (40 cols) + q, fused log_softmax ----------------
__global__ void k_aggdec(float* __restrict__ out) {
    int gw   = (blockIdx.x * blockDim.x + threadIdx.x) >> 5;
    int lane = threadIdx.x & 31;
    if (gw >= NNODES) return;
    int s = g_rowptr[gw], e = g_rowptr[gw + 1];
    bool act = lane < 20;
    float ax = 0.f, ay = 0.f;
    int i = s;
    for (; i + 1 < e; i += 2) {
        int s0 = g_col[i], s1 = g_col[i + 1];
        if (act) {
            float2 v0 = *(const float2*)(g_p + (size_t)s0 * NCLASS + lane * 2);
            float2 v1 = *(const float2*)(g_p + (size_t)s1 * NCLASS + lane * 2);
            ax += v0.x + v1.x; ay += v0.y + v1.y;
        }
    }
    if (i < e) {
        int s0 = g_col[i];
        if (act) {
            float2 v0 = *(const float2*)(g_p + (size_t)s0 * NCLASS + lane * 2);
            ax += v0.x; ay += v0.y;
        }
    }
    float inv = g_inv[gw];
    float rx = -1e30f, ry = -1e30f;
    if (act) {
        float2 qq = *(const float2*)(g_q + (size_t)gw * NCLASS + lane * 2);
        rx = ax * inv + qq.x;
        ry = ay * inv + qq.y;
    }
    float m = fmaxf(rx, ry);
    #pragma unroll
    for (int o = 16; o; o >>= 1) m = fmaxf(m, __shfl_xor_sync(0xFFFFFFFFu, m, o));
    float ss = act ? (expf(rx - m) + expf(ry - m)) : 0.f;
    #pragma unroll
    for (int o = 16; o; o >>= 1) ss += __shfl_xor_sync(0xFFFFFFFFu, ss, o);
    float l = m + logf(ss);
    if (act) {
        *(float2*)(out + (size_t)gw * NCLASS + lane * 2) = make_float2(rx - l, ry - l);
    }
}

// ---------------- launch ----------------
extern "C" void kernel_launch(void* const* d_in, const int* in_sizes, int n_in,
                              void* d_out, int out_size) {
    const float* x      = (const float*)d_in[0];
    const int*   ei     = (const int*)  d_in[1];
    const float* enc_Wl = (const float*)d_in[2];
    const float* enc_Wr = (const float*)d_in[3];
    const float* enc_b  = (const float*)d_in[4];
    const float* lay_Wl = (const float*)d_in[5];
    const float* lay_Wr = (const float*)d_in[6];
    const float* lay_b  = (const float*)d_in[7];
    const float* dec_Wl = (const float*)d_in[8];
    const float* dec_Wr = (const float*)d_in[9];
    const float* dec_b  = (const float*)d_in[10];
    float* out = (float*)d_out;

    float *agg, *hA, *hB;
    unsigned *whi, *wlo, *dhi, *dlo;
    cudaGetSymbolAddress((void**)&agg, g_agg);
    cudaGetSymbolAddress((void**)&hA,  g_hA);
    cudaGetSymbolAddress((void**)&hB,  g_hB);
    cudaGetSymbolAddress((void**)&whi, g_Whi);
    cudaGetSymbolAddress((void**)&wlo, g_Wlo);
    cudaGetSymbolAddress((void**)&dhi, g_Dhi);
    cudaGetSymbolAddress((void**)&dlo, g_Dlo);

    const int ZB = (NNODES + 255) / 256;
    const int EB = (NEDGES + 255) / 256;
    const int AGGB = (NNODES * 32 + 255) / 256;   // warp per node
    const int MB = (NNODES + 127) / 128;          // GEMM row-tiles
    const int SW = (6 * 16384 + 2 * 5120 + 255) / 256;

    k_splitW<<<SW, 256>>>(enc_Wl, enc_Wr, lay_Wl, lay_Wr, dec_Wl, dec_Wr);
    k_zero<<<ZB, 256>>>();
    k_hist<<<EB, 256>>>(ei);
    k_scan1<<<NBLK, 256>>>();
    k_scan2<<<1, 256>>>();
    k_scan3<<<NBLK, 256>>>();
    k_fill<<<EB, 256>>>(ei);

    // encoder
    k_aggregate<<<AGGB, 256>>>(x, agg);
    k_gemm128<<<MB, 256>>>(agg, x, whi, wlo, whi + 16384, wlo + 16384, enc_b, hA);
    // layer 0
    k_aggregate<<<AGGB, 256>>>(hA, agg);
    k_gemm128<<<MB, 256>>>(agg, hA, whi + 2 * 16384, wlo + 2 * 16384,
                           whi + 3 * 16384, wlo + 3 * 16384, lay_b, hB);
    // layer 1
    k_aggregate<<<AGGB, 256>>>(hB, agg);
    k_gemm128<<<MB, 256>>>(agg, hB, whi + 4 * 16384, wlo + 4 * 16384,
                           whi + 5 * 16384, wlo + 5 * 16384, lay_b + HFEAT, hA);
    // commuted decoder: p = hA@Wl, q = hA@Wr + b; aggregate p + softmax
    k_gemm_dec2<<<MB, 256>>>(hA, dhi, dlo, dhi + 5120, dlo + 5120, dec_b);
    k_aggdec<<<AGGB, 256>>>(out);
}

// round 10
// speedup vs baseline: 1.6094x; 1.4515x over previous
#include <cuda_runtime.h>
#include <cuda_bf16.h>

#define NNODES 50000
#define NEDGES 600000
#define HFEAT  128
#define NCLASS 40
#define NEG_SLOPE 0.1f
#define NBLK 196   // ceil(NNODES/256)

// ---------------- device scratch (static, allocation-free) ----------------
__device__ int   g_deg[NNODES];
__device__ int   g_fill[NNODES];
__device__ int   g_rowptr[NNODES + 1];
__device__ int   g_col[NEDGES];
__device__ float g_inv[NNODES];
__device__ int   g_btot[NBLK];
__device__ int   g_boff[NBLK];
__device__ float g_agg[(size_t)NNODES * HFEAT];
__device__ float g_hA [(size_t)NNODES * HFEAT];
__device__ float g_hB [(size_t)NNODES * HFEAT];
// decoder partials
__device__ float g_p[(size_t)NNODES * NCLASS];
__device__ float g_q[(size_t)NNODES * NCLASS];
// pre-split packed bf16x2 weights (pairs along K): 6 matrices of [64][128]
__device__ __align__(16) unsigned g_Whi[6 * 8192];
__device__ __align__(16) unsigned g_Wlo[6 * 8192];
// dec: 2 matrices of [64][40]
__device__ __align__(16) unsigned g_Dhi[2 * 2560];
__device__ __align__(16) unsigned g_Dlo[2 * 2560];

// ---------------- helpers ----------------
// split f into bf16 hi + bf16 lo (residual), pack two adjacent-K values per u32
__device__ __forceinline__ void bf16_split2(float f0, float f1, unsigned& hi, unsigned& lo) {
    unsigned short h0 = __bfloat16_as_ushort(__float2bfloat16_rn(f0));
    unsigned short h1 = __bfloat16_as_ushort(__float2bfloat16_rn(f1));
    float r0 = f0 - __uint_as_float((unsigned)h0 << 16);
    float r1 = f1 - __uint_as_float((unsigned)h1 << 16);
    unsigned short l0 = __bfloat16_as_ushort(__float2bfloat16_rn(r0));
    unsigned short l1 = __bfloat16_as_ushort(__float2bfloat16_rn(r1));
    hi = (unsigned)h0 | ((unsigned)h1 << 16);
    lo = (unsigned)l0 | ((unsigned)l1 << 16);
}

__device__ __forceinline__ void mma_bf16(float* d, const unsigned* a, unsigned b0, unsigned b1) {
    asm volatile(
        "mma.sync.aligned.m16n8k16.row.col.f32.bf16.bf16.f32 "
        "{%0,%1,%2,%3}, {%4,%5,%6,%7}, {%8,%9}, {%0,%1,%2,%3};"
        : "+f"(d[0]), "+f"(d[1]), "+f"(d[2]), "+f"(d[3])
        : "r"(a[0]), "r"(a[1]), "r"(a[2]), "r"(a[3]), "r"(b0), "r"(b1));
}

// ---------------- weight pre-split (packed bf16x2 along K) ----------------
__global__ void k_splitW(const float* __restrict__ eWl, const float* __restrict__ eWr,
                         const float* __restrict__ lWl, const float* __restrict__ lWr,
                         const float* __restrict__ dWl, const float* __restrict__ dWr)
{
    int i = blockIdx.x * blockDim.x + threadIdx.x;
    if (i < 6 * 8192) {
        int m = i >> 13, off = i & 8191;
        const float* src = (m == 0) ? eWl : (m == 1) ? eWr : (m == 2) ? lWl :
                           (m == 3) ? lWr : (m == 4) ? lWl + 16384 : lWr + 16384;
        int kp = off >> 7, n = off & 127;
        unsigned h, l;
        bf16_split2(src[(2 * kp) * 128 + n], src[(2 * kp + 1) * 128 + n], h, l);
        g_Whi[i] = h; g_Wlo[i] = l;
    } else if (i < 6 * 8192 + 2 * 2560) {
        int j = i - 6 * 8192;
        const float* src = (j < 2560) ? dWl : dWr;
        int off = (j < 2560) ? j : j - 2560;
        int kp = off / 40, n = off % 40;
        unsigned h, l;
        bf16_split2(src[(2 * kp) * 40 + n], src[(2 * kp + 1) * 40 + n], h, l);
        g_Dhi[j] = h; g_Dlo[j] = l;
    }
}

// ---------------- CSR build ----------------
__global__ void k_zero() {
    int i = blockIdx.x * blockDim.x + threadIdx.x;
    if (i < NNODES) { g_deg[i] = 0; g_fill[i] = 0; }
}

__global__ void k_hist(const int* __restrict__ ei) {
    int e = blockIdx.x * blockDim.x + threadIdx.x;
    if (e < NEDGES) atomicAdd(&g_deg[ei[NEDGES + e]], 1);
}

__global__ void k_scan1() {
    __shared__ int wsum[8];
    int b = blockIdx.x, t = threadIdx.x;
    int idx = (b << 8) + t;
    int v = (idx < NNODES) ? g_deg[idx] : 0;
    int x = v;
    #pragma unroll
    for (int o = 1; o < 32; o <<= 1) {
        int y = __shfl_up_sync(0xFFFFFFFFu, x, o);
        if ((t & 31) >= o) x += y;
    }
    if ((t & 31) == 31) wsum[t >> 5] = x;
    __syncthreads();
    if (t == 0) {
        int c = 0;
        #pragma unroll
        for (int i = 0; i < 8; i++) { int y = wsum[i]; wsum[i] = c; c += y; }
    }
    __syncthreads();
    int incl = x + wsum[t >> 5];
    if (idx < NNODES) {
        g_rowptr[idx] = incl - v;
        g_inv[idx] = 1.0f / fmaxf((float)v, 1.0f);
    }
    if (t == 255) g_btot[b] = incl;
}

__global__ void k_scan2() {
    __shared__ int wsum[8];
    int t = threadIdx.x;
    int v = (t < NBLK) ? g_btot[t] : 0;
    int x = v;
    #pragma unroll
    for (int o = 1; o < 32; o <<= 1) {
        int y = __shfl_up_sync(0xFFFFFFFFu, x, o);
        if ((t & 31) >= o) x += y;
    }
    if ((t & 31) == 31) wsum[t >> 5] = x;
    __syncthreads();
    if (t == 0) {
        int c = 0;
        #pragma unroll
        for (int i = 0; i < 8; i++) { int y = wsum[i]; wsum[i] = c; c += y; }
    }
    __syncthreads();
    int incl = x + wsum[t >> 5];
    if (t < NBLK) g_boff[t] = incl - v;
    if (t == 255) g_rowptr[NNODES] = incl;
}

__global__ void k_scan3() {
    int b = blockIdx.x, t = threadIdx.x;
    int idx = (b << 8) + t;
    if (idx < NNODES) g_rowptr[idx] += g_boff[b];
}

__global__ void k_fill(const int* __restrict__ ei) {
    int e = blockIdx.x * blockDim.x + threadIdx.x;
    if (e < NEDGES) {
        int dst = ei[NEDGES + e];
        int pos = g_rowptr[dst] + atomicAdd(&g_fill[dst], 1);
        g_col[pos] = ei[e];
    }
}

// ---------------- mean aggregation: warp per destination node ----------------
__global__ void k_aggregate(const float* __restrict__ in, float* __restrict__ out) {
    int gw   = (blockIdx.x * blockDim.x + threadIdx.x) >> 5;
    int lane = threadIdx.x & 31;
    if (gw >= NNODES) return;
    int s = g_rowptr[gw], e = g_rowptr[gw + 1];
    float4 acc = make_float4(0.f, 0.f, 0.f, 0.f);
    int i = s;
    for (; i + 1 < e; i += 2) {
        int s0 = g_col[i], s1 = g_col[i + 1];
        float4 v0 = *(const float4*)(in + (size_t)s0 * HFEAT + lane * 4);
        float4 v1 = *(const float4*)(in + (size_t)s1 * HFEAT + lane * 4);
        acc.x += v0.x + v1.x; acc.y += v0.y + v1.y;
        acc.z += v0.z + v1.z; acc.w += v0.w + v1.w;
    }
    if (i < e) {
        int s0 = g_col[i];
        float4 v0 = *(const float4*)(in + (size_t)s0 * HFEAT + lane * 4);
        acc.x += v0.x; acc.y += v0.y; acc.z += v0.z; acc.w += v0.w;
    }
    float inv = g_inv[gw];
    float4 r = make_float4(acc.x * inv, acc.y * inv, acc.z * inv, acc.w * inv);
    *(float4*)(out + (size_t)gw * HFEAT + lane * 4) = r;
}

// ---------------- SAGE GEMM, 3xBF16 (m16n8k16), pipelined, pre-split W ----------------
#define ASTRP 12    // packed A row stride (u32) — 32-bank conflict-free for frag loads
#define BSTRP 136   // packed B row stride (u32)

__global__ void __launch_bounds__(256, 2) k_gemm128(
    const float* __restrict__ A1, const float* __restrict__ A2,
    const unsigned* __restrict__ Whi0, const unsigned* __restrict__ Wlo0,
    const unsigned* __restrict__ Whi1, const unsigned* __restrict__ Wlo1,
    const float* __restrict__ bias, float* __restrict__ out)
{
    __shared__ unsigned As_hi[128 * ASTRP];
    __shared__ unsigned As_lo[128 * ASTRP];
    __shared__ unsigned Bs_hi[8 * BSTRP];
    __shared__ unsigned Bs_lo[8 * BSTRP];

    int t = threadIdx.x;
    int lane = t & 31;
    int w = t >> 5;
    int rg = w >> 1;      // row group 0..3 (32 rows each)
    int cg = w & 1;       // col group 0..1 (64 cols each)
    int block_row = blockIdx.x * 128;

    float acc[2][8][4];
    #pragma unroll
    for (int i = 0; i < 2; i++)
        #pragma unroll
        for (int j = 0; j < 8; j++)
            #pragma unroll
            for (int q = 0; q < 4; q++) acc[i][j][q] = 0.f;

    float4 avP[2];
    uint4  bhP, blP;

    // chunk c covers K [pn*128 + (c&7)*16, +16)
    auto prefetch = [&](int c) {
        int pn = c >> 3, k0 = (c & 7) << 4;
        const float*    A  = pn ? A2 : A1;
        const unsigned* Wh = pn ? Whi1 : Whi0;
        const unsigned* Wl = pn ? Wlo1 : Wlo0;
        #pragma unroll
        for (int i = 0; i < 2; i++) {
            int idx = t + (i << 8);
            int r = idx >> 2, kk = (idx & 3) << 2;
            int gr = block_row + r;
            avP[i] = (gr < NNODES) ? *(const float4*)(A + (size_t)gr * 128 + k0 + kk)
                                   : make_float4(0.f, 0.f, 0.f, 0.f);
        }
        int kb = t >> 5, n = (t & 31) << 2;          // packed W row (k0>>1)+kb
        size_t o = (size_t)((k0 >> 1) + kb) * 128 + n;
        bhP = *(const uint4*)(Wh + o);
        blP = *(const uint4*)(Wl + o);
    };

    prefetch(0);

    #pragma unroll 1
    for (int c = 0; c < 16; ++c) {
        __syncthreads();
        #pragma unroll
        for (int i = 0; i < 2; i++) {
            int idx = t + (i << 8);
            int r = idx >> 2, kp2 = (idx & 3) << 1;   // pair offset within chunk (0,2,4,6)
            unsigned h01, l01, h23, l23;
            bf16_split2(avP[i].x, avP[i].y, h01, l01);
            bf16_split2(avP[i].z, avP[i].w, h23, l23);
            *(uint2*)&As_hi[r * ASTRP + kp2] = make_uint2(h01, h23);
            *(uint2*)&As_lo[r * ASTRP + kp2] = make_uint2(l01, l23);
        }
        {
            int kb = t >> 5, n = (t & 31) << 2;
            *(uint4*)&Bs_hi[kb * BSTRP + n] = bhP;
            *(uint4*)&Bs_lo[kb * BSTRP + n] = blP;
        }
        __syncthreads();
        if (c < 15) prefetch(c + 1);

        int kp = lane & 3;
        int rb = (rg << 5) + (lane >> 2);
        unsigned ah[2][4], al[2][4];
        #pragma unroll
        for (int i = 0; i < 2; i++) {
            int r0 = rb + (i << 4);
            ah[i][0] = As_hi[r0 * ASTRP + kp];
            ah[i][1] = As_hi[(r0 + 8) * ASTRP + kp];
            ah[i][2] = As_hi[r0 * ASTRP + kp + 4];
            ah[i][3] = As_hi[(r0 + 8) * ASTRP + kp + 4];
            al[i][0] = As_lo[r0 * ASTRP + kp];
            al[i][1] = As_lo[(r0 + 8) * ASTRP + kp];
            al[i][2] = As_lo[r0 * ASTRP + kp + 4];
            al[i][3] = As_lo[(r0 + 8) * ASTRP + kp + 4];
        }
        #pragma unroll
        for (int j = 0; j < 8; j++) {
            int n0 = (cg << 6) + (j << 3) + (lane >> 2);
            unsigned bh0 = Bs_hi[kp * BSTRP + n0];
            unsigned bh1 = Bs_hi[(kp + 4) * BSTRP + n0];
            unsigned bl0 = Bs_lo[kp * BSTRP + n0];
            unsigned bl1 = Bs_lo[(kp + 4) * BSTRP + n0];
            #pragma unroll
            for (int i = 0; i < 2; i++) {
                mma_bf16(acc[i][j], al[i], bh0, bh1);
                mma_bf16(acc[i][j], ah[i], bl0, bl1);
                mma_bf16(acc[i][j], ah[i], bh0, bh1);
            }
        }
    }

    // epilogue: bias + leaky relu
    #pragma unroll
    for (int i = 0; i < 2; i++) {
        int r0 = block_row + (rg << 5) + (i << 4) + (lane >> 2);
        #pragma unroll
        for (int j = 0; j < 8; j++) {
            int c = (cg << 6) + (j << 3) + ((lane & 3) << 1);
            float bi0 = bias[c], bi1 = bias[c + 1];
            if (r0 < NNODES) {
                float v0 = acc[i][j][0] + bi0;
                float v1 = acc[i][j][1] + bi1;
                v0 = v0 > 0.f ? v0 : NEG_SLOPE * v0;
                v1 = v1 > 0.f ? v1 : NEG_SLOPE * v1;
                *(float2*)(out + (size_t)r0 * 128 + c) = make_float2(v0, v1);
            }
            int r1 = r0 + 8;
            if (r1 < NNODES) {
                float v2 = acc[i][j][2] + bi0;
                float v3 = acc[i][j][3] + bi1;
                v2 = v2 > 0.f ? v2 : NEG_SLOPE * v2;
                v3 = v3 > 0.f ? v3 : NEG_SLOPE * v3;
                *(float2*)(out + (size_t)r1 * 128 + c) = make_float2(v2, v3);
            }
        }
    }
}

// ---------------- commuted decoder GEMM: p = A@Wl, q = A@Wr + b (N=40, K=128) ----------------
#define BSTRD 44

__global__ void __launch_bounds__(256, 2) k_gemm_dec2(
    const float* __restrict__ A,
    const unsigned* __restrict__ WlH, const unsigned* __restrict__ WlL,
    const unsigned* __restrict__ WrH, const unsigned* __restrict__ WrL,
    const float* __restrict__ bias)
{
    __shared__ unsigned As_hi[128 * ASTRP];
    __shared__ unsigned As_lo[128 * ASTRP];
    __shared__ unsigned Bs[4][8 * BSTRD];   // 0:WlH 1:WlL 2:WrH 3:WrL

    int t = threadIdx.x;
    int lane = t & 31;
    int w = t >> 5;               // warp 0..7, owns 16 rows
    int block_row = blockIdx.x * 128;

    float accp[5][4], accq[5][4];
    #pragma unroll
    for (int j = 0; j < 5; j++)
        #pragma unroll
        for (int q = 0; q < 4; q++) { accp[j][q] = 0.f; accq[j][q] = 0.f; }

    float4 avP[2];
    uint4  bP[4];
    bool bload = t < 80;

    auto prefetch = [&](int c) {
        int k0 = c << 4;
        #pragma unroll
        for (int i = 0; i < 2; i++) {
            int idx = t + (i << 8);
            int r = idx >> 2, kk = (idx & 3) << 2;
            int gr = block_row + r;
            avP[i] = (gr < NNODES) ? *(const float4*)(A + (size_t)gr * 128 + k0 + kk)
                                   : make_float4(0.f, 0.f, 0.f, 0.f);
        }
        if (bload) {
            int kp = t / 10, n = (t % 10) << 2;
            size_t o = (size_t)((k0 >> 1) + kp) * NCLASS + n;
            bP[0] = *(const uint4*)(WlH + o);
            bP[1] = *(const uint4*)(WlL + o);
            bP[2] = *(const uint4*)(WrH + o);
            bP[3] = *(const uint4*)(WrL + o);
        }
    };

    prefetch(0);

    #pragma unroll 1
    for (int c = 0; c < 8; ++c) {
        __syncthreads();
        #pragma unroll
        for (int i = 0; i < 2; i++) {
            int idx = t + (i << 8);
            int r = idx >> 2, kp2 = (idx & 3) << 1;
            unsigned h01, l01, h23, l23;
            bf16_split2(avP[i].x, avP[i].y, h01, l01);
            bf16_split2(avP[i].z, avP[i].w, h23, l23);
            *(uint2*)&As_hi[r * ASTRP + kp2] = make_uint2(h01, h23);
            *(uint2*)&As_lo[r * ASTRP + kp2] = make_uint2(l01, l23);
        }
        if (bload) {
            int kp = t / 10, n = (t % 10) << 2;
            *(uint4*)&Bs[0][kp * BSTRD + n] = bP[0];
            *(uint4*)&Bs[1][kp * BSTRD + n] = bP[1];
            *(uint4*)&Bs[2][kp * BSTRD + n] = bP[2];
            *(uint4*)&Bs[3][kp * BSTRD + n] = bP[3];
        }
        __syncthreads();
        if (c < 7) prefetch(c + 1);

        int kp = lane & 3;
        int r0 = (w << 4) + (lane >> 2);
        unsigned ah[4], al[4];
        ah[0] = As_hi[r0 * ASTRP + kp];
        ah[1] = As_hi[(r0 + 8) * ASTRP + kp];
        ah[2] = As_hi[r0 * ASTRP + kp + 4];
        ah[3] = As_hi[(r0 + 8) * ASTRP + kp + 4];
        al[0] = As_lo[r0 * ASTRP + kp];
        al[1] = As_lo[(r0 + 8) * ASTRP + kp];
        al[2] = As_lo[r0 * ASTRP + kp + 4];
        al[3] = As_lo[(r0 + 8) * ASTRP + kp + 4];
        #pragma unroll
        for (int j = 0; j < 5; j++) {
            int n0 = (j << 3) + (lane >> 2);
            unsigned bh0 = Bs[0][kp * BSTRD + n0];
            unsigned bh1 = Bs[0][(kp + 4) * BSTRD + n0];
            unsigned bl0 = Bs[1][kp * BSTRD + n0];
            unsigned bl1 = Bs[1][(kp + 4) * BSTRD + n0];
            mma_bf16(accp[j], al, bh0, bh1);
            mma_bf16(accp[j], ah, bl0, bl1);
            mma_bf16(accp[j], ah, bh0, bh1);
            unsigned ch0 = Bs[2][kp * BSTRD + n0];
            unsigned ch1 = Bs[2][(kp + 4) * BSTRD + n0];
            unsigned cl0 = Bs[3][kp * BSTRD + n0];
            unsigned cl1 = Bs[3][(kp + 4) * BSTRD + n0];
            mma_bf16(accq[j], al, ch0, ch1);
            mma_bf16(accq[j], ah, cl0, cl1);
            mma_bf16(accq[j], ah, ch0, ch1);
        }
    }

    int r0 = block_row + (w << 4) + (lane >> 2);
    int r1 = r0 + 8;
    #pragma unroll
    for (int j = 0; j < 5; j++) {
        int c = (j << 3) + ((lane & 3) << 1);
        float bi0 = bias[c], bi1 = bias[c + 1];
        if (r0 < NNODES) {
            *(float2*)(g_p + (size_t)r0 * NCLASS + c) = make_float2(accp[j][0], accp[j][1]);
            *(float2*)(g_q + (size_t)r0 * NCLASS + c) = make_float2(accq[j][0] + bi0, accq[j][1] + bi1);
        }
        if (r1 < NNODES) {
            *(float2*)(g_p + (size_t)r1 * NCLASS + c) = make_float2(accp[j][2], accp[j][3]);
            *(float2*)(g_q + (size_t)r1 * NCLASS + c) = make_float2(accq[j][2] + bi0, accq[j][3] + bi1);
        }
    }
}

// ---------------- final: aggregate p (40 cols) + q, fused log_softmax ----------------
__global__ void k_aggdec(float* __restrict__ out) {
    int gw   = (blockIdx.x * blockDim.x + threadIdx.x) >> 5;
    int lane = threadIdx.x & 31;
    if (gw >= NNODES) return;
    int s = g_rowptr[gw], e = g_rowptr[gw + 1];
    bool act = lane < 20;
    float ax = 0.f, ay = 0.f;
    int i = s;
    for (; i + 1 < e; i += 2) {
        int s0 = g_col[i], s1 = g_col[i + 1];
        if (act) {
            float2 v0 = *(const float2*)(g_p + (size_t)s0 * NCLASS + lane * 2);
            float2 v1 = *(const float2*)(g_p + (size_t)s1 * NCLASS + lane * 2);
            ax += v0.x + v1.x; ay += v0.y + v1.y;
        }
    }
    if (i < e) {
        int s0 = g_col[i];
        if (act) {
            float2 v0 = *(const float2*)(g_p + (size_t)s0 * NCLASS + lane * 2);
            ax += v0.x; ay += v0.y;
        }
    }
    float inv = g_inv[gw];
    float rx = -1e30f, ry = -1e30f;
    if (act) {
        float2 qq = *(const float2*)(g_q + (size_t)gw * NCLASS + lane * 2);
        rx = ax * inv + qq.x;
        ry = ay * inv + qq.y;
    }
    float m = fmaxf(rx, ry);
    #pragma unroll
    for (int o = 16; o; o >>= 1) m = fmaxf(m, __shfl_xor_sync(0xFFFFFFFFu, m, o));
    float ss = act ? (expf(rx - m) + expf(ry - m)) : 0.f;
    #pragma unroll
    for (int o = 16; o; o >>= 1) ss += __shfl_xor_sync(0xFFFFFFFFu, ss, o);
    float l = m + logf(ss);
    if (act) {
        *(float2*)(out + (size_t)gw * NCLASS + lane * 2) = make_float2(rx - l, ry - l);
    }
}

// ---------------- launch ----------------
extern "C" void kernel_launch(void* const* d_in, const int* in_sizes, int n_in,
                              void* d_out, int out_size) {
    const float* x      = (const float*)d_in[0];
    const int*   ei     = (const int*)  d_in[1];
    const float* enc_Wl = (const float*)d_in[2];
    const float* enc_Wr = (const float*)d_in[3];
    const float* enc_b  = (const float*)d_in[4];
    const float* lay_Wl = (const float*)d_in[5];
    const float* lay_Wr = (const float*)d_in[6];
    const float* lay_b  = (const float*)d_in[7];
    const float* dec_Wl = (const float*)d_in[8];
    const float* dec_Wr = (const float*)d_in[9];
    const float* dec_b  = (const float*)d_in[10];
    float* out = (float*)d_out;

    float *agg, *hA, *hB;
    unsigned *whi, *wlo, *dhi, *dlo;
    cudaGetSymbolAddress((void**)&agg, g_agg);
    cudaGetSymbolAddress((void**)&hA,  g_hA);
    cudaGetSymbolAddress((void**)&hB,  g_hB);
    cudaGetSymbolAddress((void**)&whi, g_Whi);
    cudaGetSymbolAddress((void**)&wlo, g_Wlo);
    cudaGetSymbolAddress((void**)&dhi, g_Dhi);
    cudaGetSymbolAddress((void**)&dlo, g_Dlo);

    const int ZB = (NNODES + 255) / 256;
    const int EB = (NEDGES + 255) / 256;
    const int AGGB = (NNODES * 32 + 255) / 256;   // warp per node
    const int MB = (NNODES + 127) / 128;          // GEMM row-tiles
    const int SW = (6 * 8192 + 2 * 2560 + 255) / 256;

    k_splitW<<<SW, 256>>>(enc_Wl, enc_Wr, lay_Wl, lay_Wr, dec_Wl, dec_Wr);
    k_zero<<<ZB, 256>>>();
    k_hist<<<EB, 256>>>(ei);
    k_scan1<<<NBLK, 256>>>();
    k_scan2<<<1, 256>>>();
    k_scan3<<<NBLK, 256>>>();
    k_fill<<<EB, 256>>>(ei);

    // encoder
    k_aggregate<<<AGGB, 256>>>(x, agg);
    k_gemm128<<<MB, 256>>>(agg, x, whi, wlo, whi + 8192, wlo + 8192, enc_b, hA);
    // layer 0
    k_aggregate<<<AGGB, 256>>>(hA, agg);
    k_gemm128<<<MB, 256>>>(agg, hA, whi + 2 * 8192, wlo + 2 * 8192,
                           whi + 3 * 8192, wlo + 3 * 8192, lay_b, hB);
    // layer 1
    k_aggregate<<<AGGB, 256>>>(hB, agg);
    k_gemm128<<<MB, 256>>>(agg, hB, whi + 4 * 8192, wlo + 4 * 8192,
                           whi + 5 * 8192, wlo + 5 * 8192, lay_b + HFEAT, hA);
    // commuted decoder: p = hA@Wl, q = hA@Wr + b; aggregate p + softmax
    k_gemm_dec2<<<MB, 256>>>(hA, dhi, dlo, dhi + 2560, dlo + 2560, dec_b);
    k_aggdec<<<AGGB, 256>>>(out);
}

// round 12
// speedup vs baseline: 1.6244x; 1.0094x over previous
#include <cuda_runtime.h>
#include <cuda_bf16.h>

#define NNODES 50000
#define NEDGES 600000
#define HFEAT  128
#define NCLASS 40
#define NEG_SLOPE 0.1f
#define NBLK 196   // ceil(NNODES/256)

// ---------------- device scratch (static, allocation-free) ----------------
__device__ int   g_deg[NNODES];
__device__ int   g_fill[NNODES];
__device__ int   g_rowptr[NNODES + 1];
__device__ int   g_col[NEDGES];
__device__ float g_inv[NNODES];
__device__ int   g_btot[NBLK];
__device__ int   g_boff[NBLK];
__device__ float g_agg[(size_t)NNODES * HFEAT];
__device__ float g_hA [(size_t)NNODES * HFEAT];
__device__ float g_hB [(size_t)NNODES * HFEAT];
// decoder partials
__device__ float g_p[(size_t)NNODES * NCLASS];
__device__ float g_q[(size_t)NNODES * NCLASS];
// pre-split packed bf16x2 weights (pairs along K): 6 matrices of [64][128]
__device__ __align__(16) unsigned g_Whi[6 * 8192];
__device__ __align__(16) unsigned g_Wlo[6 * 8192];
// dec: 2 matrices of [64][40]
__device__ __align__(16) unsigned g_Dhi[2 * 2560];
__device__ __align__(16) unsigned g_Dlo[2 * 2560];

// ---------------- helpers ----------------
__device__ __forceinline__ void bf16_split2(float f0, float f1, unsigned& hi, unsigned& lo) {
    unsigned short h0 = __bfloat16_as_ushort(__float2bfloat16_rn(f0));
    unsigned short h1 = __bfloat16_as_ushort(__float2bfloat16_rn(f1));
    float r0 = f0 - __uint_as_float((unsigned)h0 << 16);
    float r1 = f1 - __uint_as_float((unsigned)h1 << 16);
    unsigned short l0 = __bfloat16_as_ushort(__float2bfloat16_rn(r0));
    unsigned short l1 = __bfloat16_as_ushort(__float2bfloat16_rn(r1));
    hi = (unsigned)h0 | ((unsigned)h1 << 16);
    lo = (unsigned)l0 | ((unsigned)l1 << 16);
}

__device__ __forceinline__ void mma_bf16(float* d, const unsigned* a, unsigned b0, unsigned b1) {
    asm volatile(
        "mma.sync.aligned.m16n8k16.row.col.f32.bf16.bf16.f32 "
        "{%0,%1,%2,%3}, {%4,%5,%6,%7}, {%8,%9}, {%0,%1,%2,%3};"
        : "+f"(d[0]), "+f"(d[1]), "+f"(d[2]), "+f"(d[3])
        : "r"(a[0]), "r"(a[1]), "r"(a[2]), "r"(a[3]), "r"(b0), "r"(b1));
}

// ---------------- weight pre-split (packed bf16x2 along K) ----------------
__global__ void k_splitW(const float* __restrict__ eWl, const float* __restrict__ eWr,
                         const float* __restrict__ lWl, const float* __restrict__ lWr,
                         const float* __restrict__ dWl, const float* __restrict__ dWr)
{
    int i = blockIdx.x * blockDim.x + threadIdx.x;
    if (i < 6 * 8192) {
        int m = i >> 13, off = i & 8191;
        const float* src = (m == 0) ? eWl : (m == 1) ? eWr : (m == 2) ? lWl :
                           (m == 3) ? lWr : (m == 4) ? lWl + 16384 : lWr + 16384;
        int kp = off >> 7, n = off & 127;
        unsigned h, l;
        bf16_split2(src[(2 * kp) * 128 + n], src[(2 * kp + 1) * 128 + n], h, l);
        g_Whi[i] = h; g_Wlo[i] = l;
    } else if (i < 6 * 8192 + 2 * 2560) {
        int j = i - 6 * 8192;
        const float* src = (j < 2560) ? dWl : dWr;
        int off = (j < 2560) ? j : j - 2560;
        int kp = off / 40, n = off % 40;
        unsigned h, l;
        bf16_split2(src[(2 * kp) * 40 + n], src[(2 * kp + 1) * 40 + n], h, l);
        g_Dhi[j] = h; g_Dlo[j] = l;
    }
}

// ---------------- CSR build ----------------
__global__ void k_zero() {
    int i = blockIdx.x * blockDim.x + threadIdx.x;
    if (i < NNODES) { g_deg[i] = 0; g_fill[i] = 0; }
}

__global__ void k_hist(const int* __restrict__ ei) {
    int e = blockIdx.x * blockDim.x + threadIdx.x;
    if (e < NEDGES) atomicAdd(&g_deg[ei[NEDGES + e]], 1);
}

__global__ void k_scan1() {
    __shared__ int wsum[8];
    int b = blockIdx.x, t = threadIdx.x;
    int idx = (b << 8) + t;
    int v = (idx < NNODES) ? g_deg[idx] : 0;
    int x = v;
    #pragma unroll
    for (int o = 1; o < 32; o <<= 1) {
        int y = __shfl_up_sync(0xFFFFFFFFu, x, o);
        if ((t & 31) >= o) x += y;
    }
    if ((t & 31) == 31) wsum[t >> 5] = x;
    __syncthreads();
    if (t == 0) {
        int c = 0;
        #pragma unroll
        for (int i = 0; i < 8; i++) { int y = wsum[i]; wsum[i] = c; c += y; }
    }
    __syncthreads();
    int incl = x + wsum[t >> 5];
    if (idx < NNODES) {
        g_rowptr[idx] = incl - v;
        g_inv[idx] = 1.0f / fmaxf((float)v, 1.0f);
    }
    if (t == 255) g_btot[b] = incl;
}

__global__ void k_scan2() {
    __shared__ int wsum[8];
    int t = threadIdx.x;
    int v = (t < NBLK) ? g_btot[t] : 0;
    int x = v;
    #pragma unroll
    for (int o = 1; o < 32; o <<= 1) {
        int y = __shfl_up_sync(0xFFFFFFFFu, x, o);
        if ((t & 31) >= o) x += y;
    }
    if ((t & 31) == 31) wsum[t >> 5] = x;
    __syncthreads();
    if (t == 0) {
        int c = 0;
        #pragma unroll
        for (int i = 0; i < 8; i++) { int y = wsum[i]; wsum[i] = c; c += y; }
    }
    __syncthreads();
    int incl = x + wsum[t >> 5];
    if (t < NBLK) g_boff[t] = incl - v;
    if (t == 255) g_rowptr[NNODES] = incl;
}

__global__ void k_scan3() {
    int b = blockIdx.x, t = threadIdx.x;
    int idx = (b << 8) + t;
    if (idx < NNODES) g_rowptr[idx] += g_boff[b];
}

__global__ void k_fill(const int* __restrict__ ei) {
    int e = blockIdx.x * blockDim.x + threadIdx.x;
    if (e < NEDGES) {
        int dst = ei[NEDGES + e];
        int pos = g_rowptr[dst] + atomicAdd(&g_fill[dst], 1);
        g_col[pos] = ei[e];
    }
}

// ---------------- mean aggregation: warp per destination node ----------------
__global__ void k_aggregate(const float* __restrict__ in, float* __restrict__ out) {
    int gw   = (blockIdx.x * blockDim.x + threadIdx.x) >> 5;
    int lane = threadIdx.x & 31;
    if (gw >= NNODES) return;
    int s = g_rowptr[gw], e = g_rowptr[gw + 1];
    float4 acc = make_float4(0.f, 0.f, 0.f, 0.f);
    int i = s;
    for (; i + 1 < e; i += 2) {
        int s0 = g_col[i], s1 = g_col[i + 1];
        float4 v0 = *(const float4*)(in + (size_t)s0 * HFEAT + lane * 4);
        float4 v1 = *(const float4*)(in + (size_t)s1 * HFEAT + lane * 4);
        acc.x += v0.x + v1.x; acc.y += v0.y + v1.y;
        acc.z += v0.z + v1.z; acc.w += v0.w + v1.w;
    }
    if (i < e) {
        int s0 = g_col[i];
        float4 v0 = *(const float4*)(in + (size_t)s0 * HFEAT + lane * 4);
        acc.x += v0.x; acc.y += v0.y; acc.z += v0.z; acc.w += v0.w;
    }
    float inv = g_inv[gw];
    float4 r = make_float4(acc.x * inv, acc.y * inv, acc.z * inv, acc.w * inv);
    *(float4*)(out + (size_t)gw * HFEAT + lane * 4) = r;
}

// ---------------- SAGE GEMM, 3xBF16 (m16n8k16), ping-pong double buffered ----------------
#define ASTRP 12    // packed A row stride (u32)
#define BSTRP 136   // packed B row stride (u32)

__global__ void __launch_bounds__(256, 2) k_gemm128(
    const float* __restrict__ A1, const float* __restrict__ A2,
    const unsigned* __restrict__ Whi0, const unsigned* __restrict__ Wlo0,
    const unsigned* __restrict__ Whi1, const unsigned* __restrict__ Wlo1,
    const float* __restrict__ bias, float* __restrict__ out)
{
    __shared__ unsigned As_hi[2][128 * ASTRP];
    __shared__ unsigned As_lo[2][128 * ASTRP];
    __shared__ unsigned Bs_hi[2][8 * BSTRP];
    __shared__ unsigned Bs_lo[2][8 * BSTRP];

    int t = threadIdx.x;
    int lane = t & 31;
    int w = t >> 5;
    int rg = w >> 1;      // row group 0..3 (32 rows each)
    int cg = w & 1;       // col group 0..1 (64 cols each)
    int block_row = blockIdx.x * 128;

    float acc[2][8][4];
    #pragma unroll
    for (int i = 0; i < 2; i++)
        #pragma unroll
        for (int j = 0; j < 8; j++)
            #pragma unroll
            for (int q = 0; q < 4; q++) acc[i][j][q] = 0.f;

    float4 avP[2];
    uint4  bhP, blP;

    // chunk c covers K [pn*128 + (c&7)*16, +16)
    auto prefetch = [&](int c) {
        int pn = c >> 3, k0 = (c & 7) << 4;
        const float*    A  = pn ? A2 : A1;
        const unsigned* Wh = pn ? Whi1 : Whi0;
        const unsigned* Wl = pn ? Wlo1 : Wlo0;
        #pragma unroll
        for (int i = 0; i < 2; i++) {
            int idx = t + (i << 8);
            int r = idx >> 2, kk = (idx & 3) << 2;
            int gr = block_row + r;
            avP[i] = (gr < NNODES) ? *(const float4*)(A + (size_t)gr * 128 + k0 + kk)
                                   : make_float4(0.f, 0.f, 0.f, 0.f);
        }
        int kb = t >> 5, n = (t & 31) << 2;
        size_t o = (size_t)((k0 >> 1) + kb) * 128 + n;
        bhP = *(const uint4*)(Wh + o);
        blP = *(const uint4*)(Wl + o);
    };

    auto storeStage = [&](int buf) {
        #pragma unroll
        for (int i = 0; i < 2; i++) {
            int idx = t + (i << 8);
            int r = idx >> 2, kp2 = (idx & 3) << 1;
            unsigned h01, l01, h23, l23;
            bf16_split2(avP[i].x, avP[i].y, h01, l01);
            bf16_split2(avP[i].z, avP[i].w, h23, l23);
            *(uint2*)&As_hi[buf][r * ASTRP + kp2] = make_uint2(h01, h23);
            *(uint2*)&As_lo[buf][r * ASTRP + kp2] = make_uint2(l01, l23);
        }
        int kb = t >> 5, n = (t & 31) << 2;
        *(uint4*)&Bs_hi[buf][kb * BSTRP + n] = bhP;
        *(uint4*)&Bs_lo[buf][kb * BSTRP + n] = blP;
    };

    auto compute = [&](int buf) {
        int kp = lane & 3;
        int rb = (rg << 5) + (lane >> 2);
        unsigned ah[2][4], al[2][4];
        #pragma unroll
        for (int i = 0; i < 2; i++) {
            int r0 = rb + (i << 4);
            ah[i][0] = As_hi[buf][r0 * ASTRP + kp];
            ah[i][1] = As_hi[buf][(r0 + 8) * ASTRP + kp];
            ah[i][2] = As_hi[buf][r0 * ASTRP + kp + 4];
            ah[i][3] = As_hi[buf][(r0 + 8) * ASTRP + kp + 4];
            al[i][0] = As_lo[buf][r0 * ASTRP + kp];
            al[i][1] = As_lo[buf][(r0 + 8) * ASTRP + kp];
            al[i][2] = As_lo[buf][r0 * ASTRP + kp + 4];
            al[i][3] = As_lo[buf][(r0 + 8) * ASTRP + kp + 4];
        }
        #pragma unroll
        for (int j = 0; j < 8; j++) {
            int n0 = (cg << 6) + (j << 3) + (lane >> 2);
            unsigned bh0 = Bs_hi[buf][kp * BSTRP + n0];
            unsigned bh1 = Bs_hi[buf][(kp + 4) * BSTRP + n0];
            unsigned bl0 = Bs_lo[buf][kp * BSTRP + n0];
            unsigned bl1 = Bs_lo[buf][(kp + 4) * BSTRP + n0];
            #pragma unroll
            for (int i = 0; i < 2; i++) {
                mma_bf16(acc[i][j], al[i], bh0, bh1);
                mma_bf16(acc[i][j], ah[i], bl0, bl1);
                mma_bf16(acc[i][j], ah[i], bh0, bh1);
            }
        }
    };

    prefetch(0);
    storeStage(0);
    prefetch(1);
    __syncthreads();

    #pragma unroll 1
    for (int c = 0; c < 16; ++c) {
        compute(c & 1);
        if (c < 15) {
            storeStage((c + 1) & 1);
            if (c < 14) prefetch(c + 2);
            __syncthreads();
        }
    }

    // epilogue: bias + leaky relu
    #pragma unroll
    for (int i = 0; i < 2; i++) {
        int r0 = block_row + (rg << 5) + (i << 4) + (lane >> 2);
        #pragma unroll
        for (int j = 0; j < 8; j++) {
            int c = (cg << 6) + (j << 3) + ((lane & 3) << 1);
            float bi0 = bias[c], bi1 = bias[c + 1];
            if (r0 < NNODES) {
                float v0 = acc[i][j][0] + bi0;
                float v1 = acc[i][j][1] + bi1;
                v0 = v0 > 0.f ? v0 : NEG_SLOPE * v0;
                v1 = v1 > 0.f ? v1 : NEG_SLOPE * v1;
                *(float2*)(out + (size_t)r0 * 128 + c) = make_float2(v0, v1);
            }
            int r1 = r0 + 8;
            if (r1 < NNODES) {
                float v2 = acc[i][j][2] + bi0;
                float v3 = acc[i][j][3] + bi1;
                v2 = v2 > 0.f ? v2 : NEG_SLOPE * v2;
                v3 = v3 > 0.f ? v3 : NEG_SLOPE * v3;
                *(float2*)(out + (size_t)r1 * 128 + c) = make_float2(v2, v3);
            }
        }
    }
}

// ---------------- commuted decoder GEMM: p = A@Wl, q = A@Wr + b (N=40, K=128) ----------------
#define BSTRD 44

__global__ void __launch_bounds__(256, 2) k_gemm_dec2(
    const float* __restrict__ A,
    const unsigned* __restrict__ WlH, const unsigned* __restrict__ WlL,
    const unsigned* __restrict__ WrH, const unsigned* __restrict__ WrL,
    const float* __restrict__ bias)
{
    __shared__ unsigned As_hi[2][128 * ASTRP];
    __shared__ unsigned As_lo[2][128 * ASTRP];
    __shared__ unsigned Bs[2][4][8 * BSTRD];   // 0:WlH 1:WlL 2:WrH 3:WrL

    int t = threadIdx.x;
    int lane = t & 31;
    int w = t >> 5;               // warp 0..7, owns 16 rows
    int block_row = blockIdx.x * 128;

    float accp[5][4], accq[5][4];
    #pragma unroll
    for (int j = 0; j < 5; j++)
        #pragma unroll
        for (int q = 0; q < 4; q++) { accp[j][q] = 0.f; accq[j][q] = 0.f; }

    float4 avP[2];
    uint4  bP[4];
    bool bload = t < 80;

    auto prefetch = [&](int c) {
        int k0 = c << 4;
        #pragma unroll
        for (int i = 0; i < 2; i++) {
            int idx = t + (i << 8);
            int r = idx >> 2, kk = (idx & 3) << 2;
            int gr = block_row + r;
            avP[i] = (gr < NNODES) ? *(const float4*)(A + (size_t)gr * 128 + k0 + kk)
                                   : make_float4(0.f, 0.f, 0.f, 0.f);
        }
        if (bload) {
            int kp = t / 10, n = (t % 10) << 2;
            size_t o = (size_t)((k0 >> 1) + kp) * NCLASS + n;
            bP[0] = *(const uint4*)(WlH + o);
            bP[1] = *(const uint4*)(WlL + o);
            bP[2] = *(const uint4*)(WrH + o);
            bP[3] = *(const uint4*)(WrL + o);
        }
    };

    auto storeStage = [&](int buf) {
        #pragma unroll
        for (int i = 0; i < 2; i++) {
            int idx = t + (i << 8);
            int r = idx >> 2, kp2 = (idx & 3) << 1;
            unsigned h01, l01, h23, l23;
            bf16_split2(avP[i].x, avP[i].y, h01, l01);
            bf16_split2(avP[i].z, avP[i].w, h23, l23);
            *(uint2*)&As_hi[buf][r * ASTRP + kp2] = make_uint2(h01, h23);
            *(uint2*)&As_lo[buf][r * ASTRP + kp2] = make_uint2(l01, l23);
        }
        if (bload) {
            int kp = t / 10, n = (t % 10) << 2;
            *(uint4*)&Bs[buf][0][kp * BSTRD + n] = bP[0];
            *(uint4*)&Bs[buf][1][kp * BSTRD + n] = bP[1];
            *(uint4*)&Bs[buf][2][kp * BSTRD + n] = bP[2];
            *(uint4*)&Bs[buf][3][kp * BSTRD + n] = bP[3];
        }
    };

    auto compute = [&](int buf) {
        int kp = lane & 3;
        int r0 = (w << 4) + (lane >> 2);
        unsigned ah[4], al[4];
        ah[0] = As_hi[buf][r0 * ASTRP + kp];
        ah[1] = As_hi[buf][(r0 + 8) * ASTRP + kp];
        ah[2] = As_hi[buf][r0 * ASTRP + kp + 4];
        ah[3] = As_hi[buf][(r0 + 8) * ASTRP + kp + 4];
        al[0] = As_lo[buf][r0 * ASTRP + kp];
        al[1] = As_lo[buf][(r0 + 8) * ASTRP + kp];
        al[2] = As_lo[buf][r0 * ASTRP + kp + 4];
        al[3] = As_lo[buf][(r0 + 8) * ASTRP + kp + 4];
        #pragma unroll
        for (int j = 0; j < 5; j++) {
            int n0 = (j << 3) + (lane >> 2);
            unsigned bh0 = Bs[buf][0][kp * BSTRD + n0];
            unsigned bh1 = Bs[buf][0][(kp + 4) * BSTRD + n0];
            unsigned bl0 = Bs[buf][1][kp * BSTRD + n0];
            unsigned bl1 = Bs[buf][1][(kp + 4) * BSTRD + n0];
            mma_bf16(accp[j], al, bh0, bh1);
            mma_bf16(accp[j], ah, bl0, bl1);
            mma_bf16(accp[j], ah, bh0, bh1);
            unsigned ch0 = Bs[buf][2][kp * BSTRD + n0];
            unsigned ch1 = Bs[buf][2][(kp + 4) * BSTRD + n0];
            unsigned cl0 = Bs[buf][3][kp * BSTRD + n0];
            unsigned cl1 = Bs[buf][3][(kp + 4) * BSTRD + n0];
            mma_bf16(accq[j], al, ch0, ch1);
            mma_bf16(accq[j], ah, cl0, cl1);
            mma_bf16(accq[j], ah, ch0, ch1);
        }
    };

    prefetch(0);
    storeStage(0);
    prefetch(1);
    __syncthreads();

    #pragma unroll 1
    for (int c = 0; c < 8; ++c) {
        compute(c & 1);
        if (c < 7) {
            storeStage((c + 1) & 1);
            if (c < 6) prefetch(c + 2);
            __syncthreads();
        }
    }

    int r0 = block_row + (w << 4) + (lane >> 2);
    int r1 = r0 + 8;
    #pragma unroll
    for (int j = 0; j < 5; j++) {
        int c = (j << 3) + ((lane & 3) << 1);
        float bi0 = bias[c], bi1 = bias[c + 1];
        if (r0 < NNODES) {
            *(float2*)(g_p + (size_t)r0 * NCLASS + c) = make_float2(accp[j][0], accp[j][1]);
            *(float2*)(g_q + (size_t)r0 * NCLASS + c) = make_float2(accq[j][0] + bi0, accq[j][1] + bi1);
        }
        if (r1 < NNODES) {
            *(float2*)(g_p + (size_t)r1 * NCLASS + c) = make_float2(accp[j][2], accp[j][3]);
            *(float2*)(g_q + (size_t)r1 * NCLASS + c) = make_float2(accq[j][2] + bi0, accq[j][3] + bi1);
        }
    }
}

// ---------------- final: aggregate p (40 cols) + q, fused log_softmax ----------------
__global__ void k_aggdec(float* __restrict__ out) {
    int gw   = (blockIdx.x * blockDim.x + threadIdx.x) >> 5;
    int lane = threadIdx.x & 31;
    if (gw >= NNODES) return;
    int s = g_rowptr[gw], e = g_rowptr[gw + 1];
    bool act = lane < 20;
    float ax = 0.f, ay = 0.f;
    int i = s;
    for (; i + 1 < e; i += 2) {
        int s0 = g_col[i], s1 = g_col[i + 1];
        if (act) {
            float2 v0 = *(const float2*)(g_p + (size_t)s0 * NCLASS + lane * 2);
            float2 v1 = *(const float2*)(g_p + (size_t)s1 * NCLASS + lane * 2);
            ax += v0.x + v1.x; ay += v0.y + v1.y;
        }
    }
    if (i < e) {
        int s0 = g_col[i];
        if (act) {
            float2 v0 = *(const float2*)(g_p + (size_t)s0 * NCLASS + lane * 2);
            ax += v0.x; ay += v0.y;
        }
    }
    float inv = g_inv[gw];
    float rx = -1e30f, ry = -1e30f;
    if (act) {
        float2 qq = *(const float2*)(g_q + (size_t)gw * NCLASS + lane * 2);
        rx = ax * inv + qq.x;
        ry = ay * inv + qq.y;
    }
    float m = fmaxf(rx, ry);
    #pragma unroll
    for (int o = 16; o; o >>= 1) m = fmaxf(m, __shfl_xor_sync(0xFFFFFFFFu, m, o));
    float ss = act ? (expf(rx - m) + expf(ry - m)) : 0.f;
    #pragma unroll
    for (int o = 16; o; o >>= 1) ss += __shfl_xor_sync(0xFFFFFFFFu, ss, o);
    float l = m + logf(ss);
    if (act) {
        *(float2*)(out + (size_t)gw * NCLASS + lane * 2) = make_float2(rx - l, ry - l);
    }
}

// ---------------- launch ----------------
extern "C" void kernel_launch(void* const* d_in, const int* in_sizes, int n_in,
                              void* d_out, int out_size) {
    const float* x      = (const float*)d_in[0];
    const int*   ei     = (const int*)  d_in[1];
    const float* enc_Wl = (const float*)d_in[2];
    const float* enc_Wr = (const float*)d_in[3];
    const float* enc_b  = (const float*)d_in[4];
    const float* lay_Wl = (const float*)d_in[5];
    const float* lay_Wr = (const float*)d_in[6];
    const float* lay_b  = (const float*)d_in[7];
    const float* dec_Wl = (const float*)d_in[8];
    const float* dec_Wr = (const float*)d_in[9];
    const float* dec_b  = (const float*)d_in[10];
    float* out = (float*)d_out;

    float *agg, *hA, *hB;
    unsigned *whi, *wlo, *dhi, *dlo;
    cudaGetSymbolAddress((void**)&agg, g_agg);
    cudaGetSymbolAddress((void**)&hA,  g_hA);
    cudaGetSymbolAddress((void**)&hB,  g_hB);
    cudaGetSymbolAddress((void**)&whi, g_Whi);
    cudaGetSymbolAddress((void**)&wlo, g_Wlo);
    cudaGetSymbolAddress((void**)&dhi, g_Dhi);
    cudaGetSymbolAddress((void**)&dlo, g_Dlo);

    const int ZB = (NNODES + 255) / 256;
    const int EB = (NEDGES + 255) / 256;
    const int AGGB = (NNODES * 32 + 255) / 256;   // warp per node
    const int MB = (NNODES + 127) / 128;          // GEMM row-tiles
    const int SW = (6 * 8192 + 2 * 2560 + 255) / 256;

    k_splitW<<<SW, 256>>>(enc_Wl, enc_Wr, lay_Wl, lay_Wr, dec_Wl, dec_Wr);
    k_zero<<<ZB, 256>>>();
    k_hist<<<EB, 256>>>(ei);
    k_scan1<<<NBLK, 256>>>();
    k_scan2<<<1, 256>>>();
    k_scan3<<<NBLK, 256>>>();
    k_fill<<<EB, 256>>>(ei);

    // encoder
    k_aggregate<<<AGGB, 256>>>(x, agg);
    k_gemm128<<<MB, 256>>>(agg, x, whi, wlo, whi + 8192, wlo + 8192, enc_b, hA);
    // layer 0
    k_aggregate<<<AGGB, 256>>>(hA, agg);
    k_gemm128<<<MB, 256>>>(agg, hA, whi + 2 * 8192, wlo + 2 * 8192,
                           whi + 3 * 8192, wlo + 3 * 8192, lay_b, hB);
    // layer 1
    k_aggregate<<<AGGB, 256>>>(hB, agg);
    k_gemm128<<<MB, 256>>>(agg, hB, whi + 4 * 8192, wlo + 4 * 8192,
                           whi + 5 * 8192, wlo + 5 * 8192, lay_b + HFEAT, hA);
    // commuted decoder: p = hA@Wl, q = hA@Wr + b; aggregate p + softmax
    k_gemm_dec2<<<MB, 256>>>(hA, dhi, dlo, dhi + 2560, dlo + 2560, dec_b);
    k_aggdec<<<AGGB, 256>>>(out);
}